// round 10
// baseline (speedup 1.0000x reference)
#include <cuda_runtime.h>
#include <cuda_fp16.h>
#include <math.h>
#include <stdint.h>

#define N_NODES 50000
#define N_EDGES 1600000
#define D_IN    512
#define D_HEAD  64
#define H1      256   /* 4 heads * 64 */
#define D_OUT   64

// ---------------- scratch (device globals; no allocation allowed) ----------
__device__ __half g_t1h[(size_t)N_NODES * H1];          // X @ W1cat (fp16)
__device__ __half g_t2h[(size_t)N_NODES * D_OUT];       // h @ W2 (fp16)
__device__ __half g_X16[(size_t)N_NODES * D_IN];        // fp16 X
__device__ __half g_H16[(size_t)N_NODES * H1];          // elu(agg1) fp16
__device__ __half g_B1[H1 * D_IN];                      // W1 packed [N=256][K=512] fp16
__device__ __half g_B2[D_OUT * H1];                     // W2 packed [N=64][K=256] fp16
__device__ int   g_counts[N_NODES];
__device__ int   g_row_start[N_NODES + 1];
__device__ int   g_cursor[N_NODES];
__device__ int   g_sorted_dst[N_EDGES];
__device__ int   g_bsums[64];
__device__ int   g_boff[64];

// ---------------- helpers ---------------------------------------------------
__device__ __forceinline__ float eluf(float x) { return x > 0.f ? x : expm1f(x); }
__device__ __forceinline__ uint32_t smem_u32(const void* p) {
    uint32_t a;
    asm("{ .reg .u64 t; cvta.to.shared.u64 t, %1; cvt.u32.u64 %0, t; }" : "=r"(a) : "l"(p));
    return a;
}
__device__ __forceinline__ void ldsm4(uint32_t& r0, uint32_t& r1, uint32_t& r2, uint32_t& r3,
                                      uint32_t addr) {
    asm volatile("ldmatrix.sync.aligned.m8n8.x4.shared.b16 {%0,%1,%2,%3}, [%4];"
                 : "=r"(r0), "=r"(r1), "=r"(r2), "=r"(r3) : "r"(addr));
}
__device__ __forceinline__ void mma16816h(float* c, uint32_t a0, uint32_t a1, uint32_t a2,
                                          uint32_t a3, uint32_t b0, uint32_t b1) {
    asm volatile(
        "mma.sync.aligned.m16n8k16.row.col.f32.f16.f16.f32 "
        "{%0,%1,%2,%3}, {%4,%5,%6,%7}, {%8,%9}, {%0,%1,%2,%3};"
        : "+f"(c[0]), "+f"(c[1]), "+f"(c[2]), "+f"(c[3])
        : "r"(a0), "r"(a1), "r"(a2), "r"(a3), "r"(b0), "r"(b1));
}
__device__ __forceinline__ void cpa16(uint32_t saddr, const void* gaddr, int sz) {
    asm volatile("cp.async.cg.shared.global [%0], [%1], 16, %2;"
                 :: "r"(saddr), "l"(gaddr), "r"(sz));
}
#define CPA_COMMIT() asm volatile("cp.async.commit_group;" ::: "memory")

// ---------------- CSR build: histogram -> 3-phase scan -> scatter -----------
__global__ void zero_counts_kernel() {
    int i = blockIdx.x * blockDim.x + threadIdx.x;
    if (i < N_NODES) g_counts[i] = 0;
}
__global__ void hist_kernel(const int* __restrict__ ei) {
    int t = blockIdx.x * blockDim.x + threadIdx.x;
    if (t < N_EDGES / 8) {
        int4 s0 = ((const int4*)ei)[t * 2 + 0];
        int4 s1 = ((const int4*)ei)[t * 2 + 1];
        atomicAdd(&g_counts[s0.x], 1);
        atomicAdd(&g_counts[s0.y], 1);
        atomicAdd(&g_counts[s0.z], 1);
        atomicAdd(&g_counts[s0.w], 1);
        atomicAdd(&g_counts[s1.x], 1);
        atomicAdd(&g_counts[s1.y], 1);
        atomicAdd(&g_counts[s1.z], 1);
        atomicAdd(&g_counts[s1.w], 1);
    }
}
#define SCAN_NB 49   /* ceil(50000/1024) */
__global__ void __launch_bounds__(1024) scan1_kernel() {
    __shared__ int wsum[32];
    int tid = threadIdx.x, lane = tid & 31, wid = tid >> 5;
    int i = blockIdx.x * 1024 + tid;
    int v = (i < N_NODES) ? g_counts[i] : 0;
    int x = v;
    #pragma unroll
    for (int o = 1; o < 32; o <<= 1) {
        int t = __shfl_up_sync(0xffffffffu, x, o);
        if (lane >= o) x += t;
    }
    if (lane == 31) wsum[wid] = x;
    __syncthreads();
    if (wid == 0) {
        int s = wsum[lane];
        #pragma unroll
        for (int o = 1; o < 32; o <<= 1) {
            int t = __shfl_up_sync(0xffffffffu, s, o);
            if (lane >= o) s += t;
        }
        wsum[lane] = s;
    }
    __syncthreads();
    int boff = (wid > 0) ? wsum[wid - 1] : 0;
    int incl = x + boff;
    if (i < N_NODES) g_row_start[i] = incl - v;
    if (tid == 1023) g_bsums[blockIdx.x] = incl;
}
__global__ void scan2_kernel() {
    __shared__ int sh[64];
    int t = threadIdx.x;
    int v = (t < SCAN_NB) ? g_bsums[t] : 0;
    sh[t] = v;
    __syncthreads();
    #pragma unroll
    for (int o = 1; o < 64; o <<= 1) {
        int val = (t >= o) ? sh[t - o] : 0;
        __syncthreads();
        sh[t] += val;
        __syncthreads();
    }
    if (t < SCAN_NB) g_boff[t] = sh[t] - v;
}
__global__ void __launch_bounds__(1024) scan3_kernel() {
    int i = blockIdx.x * 1024 + threadIdx.x;
    if (i < N_NODES) {
        int rs = g_row_start[i] + g_boff[blockIdx.x];
        g_row_start[i] = rs;
        g_cursor[i] = rs;
    }
    if (i == 0) g_row_start[N_NODES] = N_EDGES;
}
__global__ void scatter_kernel(const int* __restrict__ ei) {
    int t = blockIdx.x * blockDim.x + threadIdx.x;
    if (t < N_EDGES / 8) {
        int4 s0 = ((const int4*)ei)[t * 2 + 0];
        int4 s1 = ((const int4*)ei)[t * 2 + 1];
        int4 d0 = ((const int4*)(ei + N_EDGES))[t * 2 + 0];
        int4 d1 = ((const int4*)(ei + N_EDGES))[t * 2 + 1];
        int p0 = atomicAdd(&g_cursor[s0.x], 1);
        int p1 = atomicAdd(&g_cursor[s0.y], 1);
        int p2 = atomicAdd(&g_cursor[s0.z], 1);
        int p3 = atomicAdd(&g_cursor[s0.w], 1);
        int p4 = atomicAdd(&g_cursor[s1.x], 1);
        int p5 = atomicAdd(&g_cursor[s1.y], 1);
        int p6 = atomicAdd(&g_cursor[s1.z], 1);
        int p7 = atomicAdd(&g_cursor[s1.w], 1);
        g_sorted_dst[p0] = d0.x;
        g_sorted_dst[p1] = d0.y;
        g_sorted_dst[p2] = d0.z;
        g_sorted_dst[p3] = d0.w;
        g_sorted_dst[p4] = d1.x;
        g_sorted_dst[p5] = d1.y;
        g_sorted_dst[p6] = d1.z;
        g_sorted_dst[p7] = d1.w;
    }
}

// ---------------- fp16 conversions ------------------------------------------
__global__ void conv_x_kernel(const float* __restrict__ X) {
    int idx = blockIdx.x * blockDim.x + threadIdx.x;    // one float4 per thread
    if (idx >= N_NODES * D_IN / 4) return;
    float4 v = ((const float4*)X)[idx];
    __half2* ph = (__half2*)g_X16;
    ph[idx * 2 + 0] = __floats2half2_rn(v.x, v.y);
    ph[idx * 2 + 1] = __floats2half2_rn(v.z, v.w);
}
__global__ void pack_b1_kernel(const float* __restrict__ W1) {
    int idx = blockIdx.x * blockDim.x + threadIdx.x;
    if (idx >= H1 * D_IN) return;
    int n = idx >> 9, k = idx & 511;
    int head = n >> 6, j = n & 63;
    g_B1[idx] = __float2half_rn(W1[head * (D_IN * D_HEAD) + k * D_HEAD + j]);
}
__global__ void pack_b2_kernel(const float* __restrict__ W2) {
    int idx = blockIdx.x * blockDim.x + threadIdx.x;
    if (idx >= D_OUT * H1) return;
    int n = idx >> 8, k = idx & 255;
    g_B2[idx] = __float2half_rn(W2[k * D_OUT + n]);
}

// ---------------- HMMA GEMM (cp.async 2-stage, fp16 x fp16, fp32 accum) -----
// 256 threads, 4x2 warps, warp tile 32x32. Occupancy experiment: minBlocks=4.
#define BKC 64
#define RS  72   /* padded row stride in fp16 elems (64 + 8) */

template <int BM, int BN, int WARPS_M, int WARPS_N>
__global__ void __launch_bounds__(WARPS_M * WARPS_N * 32, 4)
gemm_mma_kernel(const __half* __restrict__ A, const __half* __restrict__ B,
                __half* __restrict__ C, int M, int N, int K) {
    constexpr int NT = WARPS_M * WARPS_N * 32;
    constexpr int WM = BM / WARPS_M;           // 32
    constexpr int WN = BN / WARPS_N;           // 32
    constexpr int TM = WM / 16;                // 2
    constexpr int TN2 = WN / 16;               // 2
    constexpr int TN = WN / 8;                 // 4
    constexpr int SA = BM * RS;
    constexpr int SB = BN * RS;
    constexpr int STAGE = SA + SB;

    extern __shared__ __half sm[];
    const uint32_t smb = smem_u32(sm);

    const int tid = threadIdx.x;
    const int wid = tid >> 5, lane = tid & 31;
    const int wm0 = (wid / WARPS_N) * WM;
    const int wn0 = (wid % WARPS_N) * WN;
    const int m0 = blockIdx.y * BM;
    const int n0 = blockIdx.x * BN;
    const int NC = K / BKC;

    float acc[TM][TN][4];
    #pragma unroll
    for (int i = 0; i < TM; i++)
        #pragma unroll
        for (int j = 0; j < TN; j++)
            #pragma unroll
            for (int q = 0; q < 4; q++) acc[i][j][q] = 0.f;

    auto issue = [&](int c) {
        int st = c & 1;
        int kt = c * BKC;
        uint32_t aS = smb + (uint32_t)(st * STAGE) * 2;
        uint32_t bS = aS + SA * 2;
        #pragma unroll
        for (int i = tid; i < BM * 8; i += NT) {
            int row = i >> 3, seg = i & 7;
            int gm = m0 + row;
            int sz = (gm < M) ? 16 : 0;
            int gmc = gm < M ? gm : (M - 1);
            size_t gsrc = (size_t)gmc * K + kt + seg * 8;
            uint32_t so = (uint32_t)(row * RS + seg * 8) * 2;
            cpa16(aS + so, A + gsrc, sz);
        }
        #pragma unroll
        for (int i = tid; i < BN * 8; i += NT) {
            int row = i >> 3, seg = i & 7;
            size_t gsrc = (size_t)(n0 + row) * K + kt + seg * 8;
            uint32_t so = (uint32_t)(row * RS + seg * 8) * 2;
            cpa16(bS + so, B + gsrc, 16);
        }
        CPA_COMMIT();
    };

    const int ldRow = lane & 15;
    const int ldCol = (lane >> 4) * 8;

    issue(0);
    for (int c = 0; c < NC; c++) {
        bool more = (c + 1) < NC;
        if (more) issue(c + 1);
        if (more) asm volatile("cp.async.wait_group 1;" ::: "memory");
        else      asm volatile("cp.async.wait_group 0;" ::: "memory");
        __syncthreads();

        int st = c & 1;
        uint32_t aS = smb + (uint32_t)(st * STAGE) * 2;
        uint32_t bS = aS + SA * 2;

        #pragma unroll
        for (int s = 0; s < 4; s++) {
            const int kb = s * 16;
            uint32_t af[TM][4];
            #pragma unroll
            for (int t = 0; t < TM; t++) {
                uint32_t off = (uint32_t)((wm0 + t * 16 + ldRow) * RS + kb + ldCol) * 2;
                ldsm4(af[t][0], af[t][1], af[t][2], af[t][3], aS + off);
            }
            uint32_t bf[TN2][4];
            #pragma unroll
            for (int t = 0; t < TN2; t++) {
                uint32_t off = (uint32_t)((wn0 + t * 16 + ldRow) * RS + kb + ldCol) * 2;
                ldsm4(bf[t][0], bf[t][1], bf[t][2], bf[t][3], bS + off);
            }
            #pragma unroll
            for (int i = 0; i < TM; i++) {
                #pragma unroll
                for (int j = 0; j < TN; j++) {
                    int t2 = j >> 1, odd = j & 1;
                    mma16816h(acc[i][j], af[i][0], af[i][1], af[i][2], af[i][3],
                              bf[t2][odd], bf[t2][odd + 2]);
                }
            }
        }
        __syncthreads();
    }

    #pragma unroll
    for (int i = 0; i < TM; i++) {
        int r0 = m0 + wm0 + i * 16 + (lane >> 2);
        #pragma unroll
        for (int j = 0; j < TN; j++) {
            int col = n0 + wn0 + j * 8 + (lane & 3) * 2;
            if (r0 < M)
                *(__half2*)&C[(size_t)r0 * N + col] = __floats2half2_rn(acc[i][j][0], acc[i][j][1]);
            if (r0 + 8 < M)
                *(__half2*)&C[(size_t)(r0 + 8) * N + col] = __floats2half2_rn(acc[i][j][2], acc[i][j][3]);
        }
    }
}

// ---------------- layer-1 aggregate + ELU -> fp16 ---------------------------
// block per node, 128 threads, thread handles 2 features, MLP=8.
__global__ void __launch_bounds__(128) agg1_kernel() {
    int node = blockIdx.x;
    int tid = threadIdx.x;
    int beg = g_row_start[node], end = g_row_start[node + 1];
    __shared__ int sd[128];

    const __half2* t1h = (const __half2*)g_t1h;   // row = 128 half2
    float ax = 0.f, ay = 0.f;

    for (int base = beg; base < end; base += 128) {
        int n = min(128, end - base);
        if (tid < n) sd[tid] = g_sorted_dst[base + tid];
        __syncthreads();
        int e = 0;
        for (; e + 8 <= n; e += 8) {
            float2 f0 = __half22float2(t1h[(size_t)sd[e + 0] * 128 + tid]);
            float2 f1 = __half22float2(t1h[(size_t)sd[e + 1] * 128 + tid]);
            float2 f2 = __half22float2(t1h[(size_t)sd[e + 2] * 128 + tid]);
            float2 f3 = __half22float2(t1h[(size_t)sd[e + 3] * 128 + tid]);
            float2 f4 = __half22float2(t1h[(size_t)sd[e + 4] * 128 + tid]);
            float2 f5 = __half22float2(t1h[(size_t)sd[e + 5] * 128 + tid]);
            float2 f6 = __half22float2(t1h[(size_t)sd[e + 6] * 128 + tid]);
            float2 f7 = __half22float2(t1h[(size_t)sd[e + 7] * 128 + tid]);
            ax += (f0.x + f1.x) + (f2.x + f3.x) + (f4.x + f5.x) + (f6.x + f7.x);
            ay += (f0.y + f1.y) + (f2.y + f3.y) + (f4.y + f5.y) + (f6.y + f7.y);
        }
        for (; e < n; e++) {
            float2 f = __half22float2(t1h[(size_t)sd[e] * 128 + tid]);
            ax += f.x; ay += f.y;
        }
        __syncthreads();
    }
    int deg = end - beg;
    float inv = deg > 0 ? 1.f / (float)deg : 0.f;
    float o0 = eluf(ax * inv), o1 = eluf(ay * inv);
    ((__half2*)g_H16)[(size_t)node * 128 + tid] = __floats2half2_rn(o0, o1);
}

// ---------------- layer-2 aggregate (warp per node, half2 lanes) ------------
__global__ void __launch_bounds__(256) agg2_kernel(float* __restrict__ out) {
    int gw = (blockIdx.x * 256 + threadIdx.x) >> 5;
    int lane = threadIdx.x & 31;
    if (gw >= N_NODES) return;
    int beg = g_row_start[gw], end = g_row_start[gw + 1];

    const __half2* t2h = (const __half2*)g_t2h;   // row = 32 half2
    float ax = 0.f, ay = 0.f;
    for (int eb = beg; eb < end; eb += 32) {
        int n = min(32, end - eb);
        int myd = (lane < n) ? g_sorted_dst[eb + lane] : 0;
        int i = 0;
        for (; i + 2 <= n; i += 2) {
            int d0 = __shfl_sync(0xffffffffu, myd, i);
            int d1 = __shfl_sync(0xffffffffu, myd, i + 1);
            float2 v0 = __half22float2(t2h[(size_t)d0 * 32 + lane]);
            float2 v1 = __half22float2(t2h[(size_t)d1 * 32 + lane]);
            ax += v0.x + v1.x; ay += v0.y + v1.y;
        }
        for (; i < n; i++) {
            int d = __shfl_sync(0xffffffffu, myd, i);
            float2 v = __half22float2(t2h[(size_t)d * 32 + lane]);
            ax += v.x; ay += v.y;
        }
    }
    int deg = end - beg;
    float inv = deg > 0 ? 1.f / (float)deg : 0.f;
    ((float2*)(out + (size_t)gw * D_OUT))[lane] = make_float2(ax * inv, ay * inv);
}

// ---------------- launch ----------------------------------------------------
extern "C" void kernel_launch(void* const* d_in, const int* in_sizes, int n_in,
                              void* d_out, int out_size) {
    const float* X  = (const float*)d_in[0];
    const int*   ei = (const int*)d_in[1];
    const float* W1 = (const float*)d_in[2];
    const float* W2 = (const float*)d_in[3];
    float* out = (float*)d_out;

    void* p;
    cudaGetSymbolAddress(&p, g_t1h); __half* t1 = (__half*)p;
    cudaGetSymbolAddress(&p, g_t2h); __half* t2 = (__half*)p;
    cudaGetSymbolAddress(&p, g_X16); __half* X16 = (__half*)p;
    cudaGetSymbolAddress(&p, g_H16); __half* H16 = (__half*)p;
    cudaGetSymbolAddress(&p, g_B1);  __half* B1 = (__half*)p;
    cudaGetSymbolAddress(&p, g_B2);  __half* B2 = (__half*)p;

    const int SMEM = 2 * (128 + 64) * RS * 2;   // 55296
    static cudaStream_t s2 = nullptr;
    static cudaEvent_t evF = nullptr, evJ = nullptr;
    if (s2 == nullptr) {
        cudaFuncSetAttribute((const void*)gemm_mma_kernel<128, 64, 4, 2>,
                             cudaFuncAttributeMaxDynamicSharedMemorySize, SMEM);
        cudaStreamCreateWithFlags(&s2, cudaStreamNonBlocking);
        cudaEventCreateWithFlags(&evF, cudaEventDisableTiming);
        cudaEventCreateWithFlags(&evJ, cudaEventDisableTiming);
    }

    // ---- fork event (recorded first so s2's CSR chain can overlap) ----
    cudaEventRecord(evF, 0);

    // dense chain FIRST in submission order (gemm1 = 4th launch -> ncu slot)
    conv_x_kernel<<<(N_NODES * D_IN / 4 + 255) / 256, 256>>>(X);
    pack_b1_kernel<<<(H1 * D_IN + 255) / 256, 256>>>(W1);
    pack_b2_kernel<<<(D_OUT * H1 + 255) / 256, 256>>>(W2);
    {
        dim3 grid(H1 / 64, (N_NODES + 127) / 128);
        gemm_mma_kernel<128, 64, 4, 2><<<grid, 256, SMEM>>>(
            X16, B1, t1, N_NODES, H1, D_IN);
    }

    // CSR chain on s2 (depends only on evF; executes overlapped with above)
    cudaStreamWaitEvent(s2, evF, 0);
    zero_counts_kernel<<<(N_NODES + 255) / 256, 256, 0, s2>>>();
    hist_kernel<<<(N_EDGES / 8 + 255) / 256, 256, 0, s2>>>(ei);
    scan1_kernel<<<SCAN_NB, 1024, 0, s2>>>();
    scan2_kernel<<<1, 64, 0, s2>>>();
    scan3_kernel<<<SCAN_NB, 1024, 0, s2>>>();
    scatter_kernel<<<(N_EDGES / 8 + 255) / 256, 256, 0, s2>>>(ei);
    cudaEventRecord(evJ, s2);

    // ---- join ----
    cudaStreamWaitEvent(0, evJ, 0);

    agg1_kernel<<<N_NODES, 128>>>();
    {
        dim3 grid(1, (N_NODES + 127) / 128);
        gemm_mma_kernel<128, 64, 4, 2><<<grid, 256, SMEM>>>(
            H16, B2, t2, N_NODES, D_OUT, H1);
    }
    agg2_kernel<<<(N_NODES * 32 + 255) / 256, 256>>>(out);
}

// round 11
// speedup vs baseline: 1.0202x; 1.0202x over previous
#include <cuda_runtime.h>
#include <cuda_fp16.h>
#include <math.h>
#include <stdint.h>

#define N_NODES 50000
#define N_EDGES 1600000
#define D_IN    512
#define D_HEAD  64
#define H1      256   /* 4 heads * 64 */
#define D_OUT   64

// ---------------- scratch (device globals; no allocation allowed) ----------
__device__ __half g_t1h[(size_t)N_NODES * H1];          // X @ W1cat (fp16)
__device__ __half g_t2h[(size_t)N_NODES * D_OUT];       // h @ W2 (fp16)
__device__ __half g_X16[(size_t)N_NODES * D_IN];        // fp16 X
__device__ __half g_H16[(size_t)N_NODES * H1];          // elu(agg1) fp16
__device__ __half g_B1[H1 * D_IN];                      // W1 packed [N=256][K=512] fp16
__device__ __half g_B2[D_OUT * H1];                     // W2 packed [N=64][K=256] fp16
__device__ int   g_counts[N_NODES];
__device__ int   g_row_start[N_NODES + 1];
__device__ int   g_cursor[N_NODES];
__device__ int   g_sorted_dst[N_EDGES];
__device__ int   g_bsums[64];
__device__ int   g_boff[64];

// ---------------- helpers ---------------------------------------------------
__device__ __forceinline__ float eluf(float x) { return x > 0.f ? x : expm1f(x); }
__device__ __forceinline__ uint32_t smem_u32(const void* p) {
    uint32_t a;
    asm("{ .reg .u64 t; cvta.to.shared.u64 t, %1; cvt.u32.u64 %0, t; }" : "=r"(a) : "l"(p));
    return a;
}
__device__ __forceinline__ void ldsm4(uint32_t& r0, uint32_t& r1, uint32_t& r2, uint32_t& r3,
                                      uint32_t addr) {
    asm volatile("ldmatrix.sync.aligned.m8n8.x4.shared.b16 {%0,%1,%2,%3}, [%4];"
                 : "=r"(r0), "=r"(r1), "=r"(r2), "=r"(r3) : "r"(addr));
}
__device__ __forceinline__ void mma16816h(float* c, uint32_t a0, uint32_t a1, uint32_t a2,
                                          uint32_t a3, uint32_t b0, uint32_t b1) {
    asm volatile(
        "mma.sync.aligned.m16n8k16.row.col.f32.f16.f16.f32 "
        "{%0,%1,%2,%3}, {%4,%5,%6,%7}, {%8,%9}, {%0,%1,%2,%3};"
        : "+f"(c[0]), "+f"(c[1]), "+f"(c[2]), "+f"(c[3])
        : "r"(a0), "r"(a1), "r"(a2), "r"(a3), "r"(b0), "r"(b1));
}
__device__ __forceinline__ void cpa16(uint32_t saddr, const void* gaddr, int sz) {
    asm volatile("cp.async.cg.shared.global [%0], [%1], 16, %2;"
                 :: "r"(saddr), "l"(gaddr), "r"(sz));
}
#define CPA_COMMIT() asm volatile("cp.async.commit_group;" ::: "memory")

// ---------------- CSR build: histogram -> 3-phase scan -> scatter -----------
__global__ void zero_counts_kernel() {
    int i = blockIdx.x * blockDim.x + threadIdx.x;
    if (i < N_NODES) g_counts[i] = 0;
}
__global__ void hist_kernel(const int* __restrict__ ei) {
    int t = blockIdx.x * blockDim.x + threadIdx.x;
    if (t < N_EDGES / 8) {
        int4 s0 = ((const int4*)ei)[t * 2 + 0];
        int4 s1 = ((const int4*)ei)[t * 2 + 1];
        atomicAdd(&g_counts[s0.x], 1);
        atomicAdd(&g_counts[s0.y], 1);
        atomicAdd(&g_counts[s0.z], 1);
        atomicAdd(&g_counts[s0.w], 1);
        atomicAdd(&g_counts[s1.x], 1);
        atomicAdd(&g_counts[s1.y], 1);
        atomicAdd(&g_counts[s1.z], 1);
        atomicAdd(&g_counts[s1.w], 1);
    }
}
#define SCAN_NB 49   /* ceil(50000/1024) */
__global__ void __launch_bounds__(1024) scan1_kernel() {
    __shared__ int wsum[32];
    int tid = threadIdx.x, lane = tid & 31, wid = tid >> 5;
    int i = blockIdx.x * 1024 + tid;
    int v = (i < N_NODES) ? g_counts[i] : 0;
    int x = v;
    #pragma unroll
    for (int o = 1; o < 32; o <<= 1) {
        int t = __shfl_up_sync(0xffffffffu, x, o);
        if (lane >= o) x += t;
    }
    if (lane == 31) wsum[wid] = x;
    __syncthreads();
    if (wid == 0) {
        int s = wsum[lane];
        #pragma unroll
        for (int o = 1; o < 32; o <<= 1) {
            int t = __shfl_up_sync(0xffffffffu, s, o);
            if (lane >= o) s += t;
        }
        wsum[lane] = s;
    }
    __syncthreads();
    int boff = (wid > 0) ? wsum[wid - 1] : 0;
    int incl = x + boff;
    if (i < N_NODES) g_row_start[i] = incl - v;
    if (tid == 1023) g_bsums[blockIdx.x] = incl;
}
__global__ void scan2_kernel() {
    __shared__ int sh[64];
    int t = threadIdx.x;
    int v = (t < SCAN_NB) ? g_bsums[t] : 0;
    sh[t] = v;
    __syncthreads();
    #pragma unroll
    for (int o = 1; o < 64; o <<= 1) {
        int val = (t >= o) ? sh[t - o] : 0;
        __syncthreads();
        sh[t] += val;
        __syncthreads();
    }
    if (t < SCAN_NB) g_boff[t] = sh[t] - v;
}
__global__ void __launch_bounds__(1024) scan3_kernel() {
    int i = blockIdx.x * 1024 + threadIdx.x;
    if (i < N_NODES) {
        int rs = g_row_start[i] + g_boff[blockIdx.x];
        g_row_start[i] = rs;
        g_cursor[i] = rs;
    }
    if (i == 0) g_row_start[N_NODES] = N_EDGES;
}
__global__ void scatter_kernel(const int* __restrict__ ei) {
    int t = blockIdx.x * blockDim.x + threadIdx.x;
    if (t < N_EDGES / 8) {
        int4 s0 = ((const int4*)ei)[t * 2 + 0];
        int4 s1 = ((const int4*)ei)[t * 2 + 1];
        int4 d0 = ((const int4*)(ei + N_EDGES))[t * 2 + 0];
        int4 d1 = ((const int4*)(ei + N_EDGES))[t * 2 + 1];
        int p0 = atomicAdd(&g_cursor[s0.x], 1);
        int p1 = atomicAdd(&g_cursor[s0.y], 1);
        int p2 = atomicAdd(&g_cursor[s0.z], 1);
        int p3 = atomicAdd(&g_cursor[s0.w], 1);
        int p4 = atomicAdd(&g_cursor[s1.x], 1);
        int p5 = atomicAdd(&g_cursor[s1.y], 1);
        int p6 = atomicAdd(&g_cursor[s1.z], 1);
        int p7 = atomicAdd(&g_cursor[s1.w], 1);
        g_sorted_dst[p0] = d0.x;
        g_sorted_dst[p1] = d0.y;
        g_sorted_dst[p2] = d0.z;
        g_sorted_dst[p3] = d0.w;
        g_sorted_dst[p4] = d1.x;
        g_sorted_dst[p5] = d1.y;
        g_sorted_dst[p6] = d1.z;
        g_sorted_dst[p7] = d1.w;
    }
}

// ---------------- fused prep: X->fp16 + pack W1 + pack W2 -------------------
#define NXITEMS (N_NODES * D_IN / 4)                 /* 6,400,000 float4 */
#define NW1ITEMS (H1 * D_IN)                         /* 131,072 */
#define NW2ITEMS (D_OUT * H1)                        /* 16,384 */
__global__ void prep_kernel(const float* __restrict__ X,
                            const float* __restrict__ W1,
                            const float* __restrict__ W2) {
    int idx = blockIdx.x * blockDim.x + threadIdx.x;
    if (idx < NXITEMS) {
        float4 v = ((const float4*)X)[idx];
        __half2* ph = (__half2*)g_X16;
        ph[idx * 2 + 0] = __floats2half2_rn(v.x, v.y);
        ph[idx * 2 + 1] = __floats2half2_rn(v.z, v.w);
    } else if (idx < NXITEMS + NW1ITEMS) {
        int i2 = idx - NXITEMS;
        int n = i2 >> 9, k = i2 & 511;
        int head = n >> 6, j = n & 63;
        g_B1[i2] = __float2half_rn(W1[head * (D_IN * D_HEAD) + k * D_HEAD + j]);
    } else if (idx < NXITEMS + NW1ITEMS + NW2ITEMS) {
        int i2 = idx - NXITEMS - NW1ITEMS;
        int n = i2 >> 8, k = i2 & 255;
        g_B2[i2] = __float2half_rn(W2[k * D_OUT + n]);
    }
}

// ---------------- HMMA GEMM (cp.async 2-stage, fp16 x fp16, fp32 accum) -----
// PROVEN R7 shape: 256 threads, 4x2 warps, warp tile 32x32, minBlocks=3.
#define BKC 64
#define RS  72   /* padded row stride in fp16 elems (64 + 8) */

template <int BM, int BN, int WARPS_M, int WARPS_N>
__global__ void __launch_bounds__(WARPS_M * WARPS_N * 32, 3)
gemm_mma_kernel(const __half* __restrict__ A, const __half* __restrict__ B,
                __half* __restrict__ C, int M, int N, int K) {
    constexpr int NT = WARPS_M * WARPS_N * 32;
    constexpr int WM = BM / WARPS_M;           // 32
    constexpr int WN = BN / WARPS_N;           // 32
    constexpr int TM = WM / 16;                // 2
    constexpr int TN2 = WN / 16;               // 2
    constexpr int TN = WN / 8;                 // 4
    constexpr int SA = BM * RS;
    constexpr int SB = BN * RS;
    constexpr int STAGE = SA + SB;

    extern __shared__ __half sm[];
    const uint32_t smb = smem_u32(sm);

    const int tid = threadIdx.x;
    const int wid = tid >> 5, lane = tid & 31;
    const int wm0 = (wid / WARPS_N) * WM;
    const int wn0 = (wid % WARPS_N) * WN;
    const int m0 = blockIdx.y * BM;
    const int n0 = blockIdx.x * BN;
    const int NC = K / BKC;

    float acc[TM][TN][4];
    #pragma unroll
    for (int i = 0; i < TM; i++)
        #pragma unroll
        for (int j = 0; j < TN; j++)
            #pragma unroll
            for (int q = 0; q < 4; q++) acc[i][j][q] = 0.f;

    auto issue = [&](int c) {
        int st = c & 1;
        int kt = c * BKC;
        uint32_t aS = smb + (uint32_t)(st * STAGE) * 2;
        uint32_t bS = aS + SA * 2;
        #pragma unroll
        for (int i = tid; i < BM * 8; i += NT) {
            int row = i >> 3, seg = i & 7;
            int gm = m0 + row;
            int sz = (gm < M) ? 16 : 0;
            int gmc = gm < M ? gm : (M - 1);
            size_t gsrc = (size_t)gmc * K + kt + seg * 8;
            uint32_t so = (uint32_t)(row * RS + seg * 8) * 2;
            cpa16(aS + so, A + gsrc, sz);
        }
        #pragma unroll
        for (int i = tid; i < BN * 8; i += NT) {
            int row = i >> 3, seg = i & 7;
            size_t gsrc = (size_t)(n0 + row) * K + kt + seg * 8;
            uint32_t so = (uint32_t)(row * RS + seg * 8) * 2;
            cpa16(bS + so, B + gsrc, 16);
        }
        CPA_COMMIT();
    };

    const int ldRow = lane & 15;
    const int ldCol = (lane >> 4) * 8;

    issue(0);
    for (int c = 0; c < NC; c++) {
        bool more = (c + 1) < NC;
        if (more) issue(c + 1);
        if (more) asm volatile("cp.async.wait_group 1;" ::: "memory");
        else      asm volatile("cp.async.wait_group 0;" ::: "memory");
        __syncthreads();

        int st = c & 1;
        uint32_t aS = smb + (uint32_t)(st * STAGE) * 2;
        uint32_t bS = aS + SA * 2;

        #pragma unroll
        for (int s = 0; s < 4; s++) {
            const int kb = s * 16;
            uint32_t af[TM][4];
            #pragma unroll
            for (int t = 0; t < TM; t++) {
                uint32_t off = (uint32_t)((wm0 + t * 16 + ldRow) * RS + kb + ldCol) * 2;
                ldsm4(af[t][0], af[t][1], af[t][2], af[t][3], aS + off);
            }
            uint32_t bf[TN2][4];
            #pragma unroll
            for (int t = 0; t < TN2; t++) {
                uint32_t off = (uint32_t)((wn0 + t * 16 + ldRow) * RS + kb + ldCol) * 2;
                ldsm4(bf[t][0], bf[t][1], bf[t][2], bf[t][3], bS + off);
            }
            #pragma unroll
            for (int i = 0; i < TM; i++) {
                #pragma unroll
                for (int j = 0; j < TN; j++) {
                    int t2 = j >> 1, odd = j & 1;
                    mma16816h(acc[i][j], af[i][0], af[i][1], af[i][2], af[i][3],
                              bf[t2][odd], bf[t2][odd + 2]);
                }
            }
        }
        __syncthreads();
    }

    #pragma unroll
    for (int i = 0; i < TM; i++) {
        int r0 = m0 + wm0 + i * 16 + (lane >> 2);
        #pragma unroll
        for (int j = 0; j < TN; j++) {
            int col = n0 + wn0 + j * 8 + (lane & 3) * 2;
            if (r0 < M)
                *(__half2*)&C[(size_t)r0 * N + col] = __floats2half2_rn(acc[i][j][0], acc[i][j][1]);
            if (r0 + 8 < M)
                *(__half2*)&C[(size_t)(r0 + 8) * N + col] = __floats2half2_rn(acc[i][j][2], acc[i][j][3]);
        }
    }
}

// ---------------- layer-1 aggregate + ELU -> fp16 (R7 exact) ----------------
__global__ void __launch_bounds__(128) agg1_kernel() {
    int node = blockIdx.x;
    int tid = threadIdx.x;
    int beg = g_row_start[node], end = g_row_start[node + 1];
    __shared__ int sd[128];

    const __half2* t1h = (const __half2*)g_t1h;   // row = 128 half2
    float ax = 0.f, ay = 0.f;

    for (int base = beg; base < end; base += 128) {
        int n = min(128, end - base);
        if (tid < n) sd[tid] = g_sorted_dst[base + tid];
        __syncthreads();
        int e = 0;
        for (; e + 4 <= n; e += 4) {
            int d0 = sd[e], d1 = sd[e + 1], d2 = sd[e + 2], d3 = sd[e + 3];
            float2 f0 = __half22float2(t1h[(size_t)d0 * 128 + tid]);
            float2 f1 = __half22float2(t1h[(size_t)d1 * 128 + tid]);
            float2 f2 = __half22float2(t1h[(size_t)d2 * 128 + tid]);
            float2 f3 = __half22float2(t1h[(size_t)d3 * 128 + tid]);
            ax += f0.x + f1.x + f2.x + f3.x;
            ay += f0.y + f1.y + f2.y + f3.y;
        }
        for (; e < n; e++) {
            float2 f = __half22float2(t1h[(size_t)sd[e] * 128 + tid]);
            ax += f.x; ay += f.y;
        }
        __syncthreads();
    }
    int deg = end - beg;
    float inv = deg > 0 ? 1.f / (float)deg : 0.f;
    float o0 = eluf(ax * inv), o1 = eluf(ay * inv);
    ((__half2*)g_H16)[(size_t)node * 128 + tid] = __floats2half2_rn(o0, o1);
}

// ---------------- layer-2 aggregate (warp per node, half2 lanes) ------------
__global__ void __launch_bounds__(256) agg2_kernel(float* __restrict__ out) {
    int gw = (blockIdx.x * 256 + threadIdx.x) >> 5;
    int lane = threadIdx.x & 31;
    if (gw >= N_NODES) return;
    int beg = g_row_start[gw], end = g_row_start[gw + 1];

    const __half2* t2h = (const __half2*)g_t2h;   // row = 32 half2
    float ax = 0.f, ay = 0.f;
    for (int eb = beg; eb < end; eb += 32) {
        int n = min(32, end - eb);
        int myd = (lane < n) ? g_sorted_dst[eb + lane] : 0;
        int i = 0;
        for (; i + 2 <= n; i += 2) {
            int d0 = __shfl_sync(0xffffffffu, myd, i);
            int d1 = __shfl_sync(0xffffffffu, myd, i + 1);
            float2 v0 = __half22float2(t2h[(size_t)d0 * 32 + lane]);
            float2 v1 = __half22float2(t2h[(size_t)d1 * 32 + lane]);
            ax += v0.x + v1.x; ay += v0.y + v1.y;
        }
        for (; i < n; i++) {
            int d = __shfl_sync(0xffffffffu, myd, i);
            float2 v = __half22float2(t2h[(size_t)d * 32 + lane]);
            ax += v.x; ay += v.y;
        }
    }
    int deg = end - beg;
    float inv = deg > 0 ? 1.f / (float)deg : 0.f;
    ((float2*)(out + (size_t)gw * D_OUT))[lane] = make_float2(ax * inv, ay * inv);
}

// ---------------- launch (R7 structure: CSR first on s2, dense on main) -----
extern "C" void kernel_launch(void* const* d_in, const int* in_sizes, int n_in,
                              void* d_out, int out_size) {
    const float* X  = (const float*)d_in[0];
    const int*   ei = (const int*)d_in[1];
    const float* W1 = (const float*)d_in[2];
    const float* W2 = (const float*)d_in[3];
    float* out = (float*)d_out;

    void* p;
    cudaGetSymbolAddress(&p, g_t1h); __half* t1 = (__half*)p;
    cudaGetSymbolAddress(&p, g_t2h); __half* t2 = (__half*)p;
    cudaGetSymbolAddress(&p, g_X16); __half* X16 = (__half*)p;
    cudaGetSymbolAddress(&p, g_H16); __half* H16 = (__half*)p;
    cudaGetSymbolAddress(&p, g_B1);  __half* B1 = (__half*)p;
    cudaGetSymbolAddress(&p, g_B2);  __half* B2 = (__half*)p;

    const int SMEM = 2 * (128 + 64) * RS * 2;   // 55296
    static cudaStream_t s2 = nullptr;
    static cudaEvent_t evF = nullptr, evJ = nullptr;
    if (s2 == nullptr) {
        cudaFuncSetAttribute((const void*)gemm_mma_kernel<128, 64, 4, 2>,
                             cudaFuncAttributeMaxDynamicSharedMemorySize, SMEM);
        cudaStreamCreateWithFlags(&s2, cudaStreamNonBlocking);
        cudaEventCreateWithFlags(&evF, cudaEventDisableTiming);
        cudaEventCreateWithFlags(&evJ, cudaEventDisableTiming);
    }

    // ---- fork: CSR chain on s2, dense chain on origin stream ----
    cudaEventRecord(evF, 0);
    cudaStreamWaitEvent(s2, evF, 0);

    zero_counts_kernel<<<(N_NODES + 255) / 256, 256, 0, s2>>>();
    hist_kernel<<<(N_EDGES / 8 + 255) / 256, 256, 0, s2>>>(ei);
    scan1_kernel<<<SCAN_NB, 1024, 0, s2>>>();
    scan2_kernel<<<1, 64, 0, s2>>>();
    scan3_kernel<<<SCAN_NB, 1024, 0, s2>>>();
    scatter_kernel<<<(N_EDGES / 8 + 255) / 256, 256, 0, s2>>>(ei);
    cudaEventRecord(evJ, s2);

    // dense chain (origin stream): fused prep then gemm1
    prep_kernel<<<(NXITEMS + NW1ITEMS + NW2ITEMS + 255) / 256, 256>>>(X, W1, W2);
    {
        dim3 grid(H1 / 64, (N_NODES + 127) / 128);
        gemm_mma_kernel<128, 64, 4, 2><<<grid, 256, SMEM>>>(
            X16, B1, t1, N_NODES, H1, D_IN);
    }

    // ---- join ----
    cudaStreamWaitEvent(0, evJ, 0);

    agg1_kernel<<<N_NODES, 128>>>();
    {
        dim3 grid(1, (N_NODES + 127) / 128);
        gemm_mma_kernel<128, 64, 4, 2><<<grid, 256, SMEM>>>(
            H16, B2, t2, N_NODES, D_OUT, H1);
    }
    agg2_kernel<<<(N_NODES * 32 + 255) / 256, 256>>>(out);
}

// round 12
// speedup vs baseline: 1.0399x; 1.0193x over previous
#include <cuda_runtime.h>
#include <cuda_fp16.h>
#include <math.h>
#include <stdint.h>

#define N_NODES 50000
#define N_EDGES 1600000
#define D_IN    512
#define D_HEAD  64
#define H1      256   /* 4 heads * 64 */
#define D_OUT   64

// ---------------- scratch (device globals; no allocation allowed) ----------
__device__ __half g_t1h[(size_t)N_NODES * H1];          // X @ W1cat (fp16)
__device__ __half g_t2h[(size_t)N_NODES * D_OUT];       // h @ W2 (fp16)
__device__ __half g_X16[(size_t)N_NODES * D_IN];        // fp16 X
__device__ __half g_H16[(size_t)N_NODES * H1];          // elu(agg1) fp16
__device__ __half g_B1[H1 * D_IN];                      // W1 packed [N=256][K=512] fp16
__device__ __half g_B2[D_OUT * H1];                     // W2 packed [N=64][K=256] fp16
__device__ int   g_counts[N_NODES];
__device__ int   g_row_start[N_NODES + 1];
__device__ int   g_cursor[N_NODES];
__device__ int   g_sorted_dst[N_EDGES];
__device__ int   g_bsums[64];
__device__ int   g_boff[64];

// ---------------- helpers ---------------------------------------------------
__device__ __forceinline__ float eluf(float x) { return x > 0.f ? x : expm1f(x); }
__device__ __forceinline__ uint32_t smem_u32(const void* p) {
    uint32_t a;
    asm("{ .reg .u64 t; cvta.to.shared.u64 t, %1; cvt.u32.u64 %0, t; }" : "=r"(a) : "l"(p));
    return a;
}
__device__ __forceinline__ void ldsm4(uint32_t& r0, uint32_t& r1, uint32_t& r2, uint32_t& r3,
                                      uint32_t addr) {
    asm volatile("ldmatrix.sync.aligned.m8n8.x4.shared.b16 {%0,%1,%2,%3}, [%4];"
                 : "=r"(r0), "=r"(r1), "=r"(r2), "=r"(r3) : "r"(addr));
}
__device__ __forceinline__ void mma16816h(float* c, uint32_t a0, uint32_t a1, uint32_t a2,
                                          uint32_t a3, uint32_t b0, uint32_t b1) {
    asm volatile(
        "mma.sync.aligned.m16n8k16.row.col.f32.f16.f16.f32 "
        "{%0,%1,%2,%3}, {%4,%5,%6,%7}, {%8,%9}, {%0,%1,%2,%3};"
        : "+f"(c[0]), "+f"(c[1]), "+f"(c[2]), "+f"(c[3])
        : "r"(a0), "r"(a1), "r"(a2), "r"(a3), "r"(b0), "r"(b1));
}
__device__ __forceinline__ void cpa16(uint32_t saddr, const void* gaddr, int sz) {
    asm volatile("cp.async.cg.shared.global [%0], [%1], 16, %2;"
                 :: "r"(saddr), "l"(gaddr), "r"(sz));
}
#define CPA_COMMIT() asm volatile("cp.async.commit_group;" ::: "memory")

// ---------------- CSR build: histogram -> 3-phase scan -> scatter -----------
// R5/R7-proven 4-edge-per-thread versions (8-wide regressed: scatter is
// latency-bound and longer per-thread chains halve TLP).
__global__ void zero_counts_kernel() {
    int i = blockIdx.x * blockDim.x + threadIdx.x;
    if (i < N_NODES) g_counts[i] = 0;
}
__global__ void hist_kernel(const int* __restrict__ ei) {
    int t = blockIdx.x * blockDim.x + threadIdx.x;
    if (t < N_EDGES / 4) {
        int4 s = ((const int4*)ei)[t];
        atomicAdd(&g_counts[s.x], 1);
        atomicAdd(&g_counts[s.y], 1);
        atomicAdd(&g_counts[s.z], 1);
        atomicAdd(&g_counts[s.w], 1);
    }
}
#define SCAN_NB 49   /* ceil(50000/1024) */
__global__ void __launch_bounds__(1024) scan1_kernel() {
    __shared__ int wsum[32];
    int tid = threadIdx.x, lane = tid & 31, wid = tid >> 5;
    int i = blockIdx.x * 1024 + tid;
    int v = (i < N_NODES) ? g_counts[i] : 0;
    int x = v;
    #pragma unroll
    for (int o = 1; o < 32; o <<= 1) {
        int t = __shfl_up_sync(0xffffffffu, x, o);
        if (lane >= o) x += t;
    }
    if (lane == 31) wsum[wid] = x;
    __syncthreads();
    if (wid == 0) {
        int s = wsum[lane];
        #pragma unroll
        for (int o = 1; o < 32; o <<= 1) {
            int t = __shfl_up_sync(0xffffffffu, s, o);
            if (lane >= o) s += t;
        }
        wsum[lane] = s;
    }
    __syncthreads();
    int boff = (wid > 0) ? wsum[wid - 1] : 0;
    int incl = x + boff;
    if (i < N_NODES) g_row_start[i] = incl - v;
    if (tid == 1023) g_bsums[blockIdx.x] = incl;
}
__global__ void scan2_kernel() {
    __shared__ int sh[64];
    int t = threadIdx.x;
    int v = (t < SCAN_NB) ? g_bsums[t] : 0;
    sh[t] = v;
    __syncthreads();
    #pragma unroll
    for (int o = 1; o < 64; o <<= 1) {
        int val = (t >= o) ? sh[t - o] : 0;
        __syncthreads();
        sh[t] += val;
        __syncthreads();
    }
    if (t < SCAN_NB) g_boff[t] = sh[t] - v;
}
__global__ void __launch_bounds__(1024) scan3_kernel() {
    int i = blockIdx.x * 1024 + threadIdx.x;
    if (i < N_NODES) {
        int rs = g_row_start[i] + g_boff[blockIdx.x];
        g_row_start[i] = rs;
        g_cursor[i] = rs;
    }
    if (i == 0) g_row_start[N_NODES] = N_EDGES;
}
__global__ void scatter_kernel(const int* __restrict__ ei) {
    int t = blockIdx.x * blockDim.x + threadIdx.x;
    if (t < N_EDGES / 4) {
        int4 s = ((const int4*)ei)[t];
        int4 d = ((const int4*)(ei + N_EDGES))[t];
        int p0 = atomicAdd(&g_cursor[s.x], 1);
        int p1 = atomicAdd(&g_cursor[s.y], 1);
        int p2 = atomicAdd(&g_cursor[s.z], 1);
        int p3 = atomicAdd(&g_cursor[s.w], 1);
        g_sorted_dst[p0] = d.x;
        g_sorted_dst[p1] = d.y;
        g_sorted_dst[p2] = d.z;
        g_sorted_dst[p3] = d.w;
    }
}

// ---------------- fused prep: X->fp16 + pack W1 + pack W2 -------------------
#define NXITEMS (N_NODES * D_IN / 4)                 /* 6,400,000 float4 */
#define NW1ITEMS (H1 * D_IN)                         /* 131,072 */
#define NW2ITEMS (D_OUT * H1)                        /* 16,384 */
__global__ void prep_kernel(const float* __restrict__ X,
                            const float* __restrict__ W1,
                            const float* __restrict__ W2) {
    int idx = blockIdx.x * blockDim.x + threadIdx.x;
    if (idx < NXITEMS) {
        float4 v = ((const float4*)X)[idx];
        __half2* ph = (__half2*)g_X16;
        ph[idx * 2 + 0] = __floats2half2_rn(v.x, v.y);
        ph[idx * 2 + 1] = __floats2half2_rn(v.z, v.w);
    } else if (idx < NXITEMS + NW1ITEMS) {
        int i2 = idx - NXITEMS;
        int n = i2 >> 9, k = i2 & 511;
        int head = n >> 6, j = n & 63;
        g_B1[i2] = __float2half_rn(W1[head * (D_IN * D_HEAD) + k * D_HEAD + j]);
    } else if (idx < NXITEMS + NW1ITEMS + NW2ITEMS) {
        int i2 = idx - NXITEMS - NW1ITEMS;
        int n = i2 >> 8, k = i2 & 255;
        g_B2[i2] = __float2half_rn(W2[k * D_OUT + n]);
    }
}

// ---------------- HMMA GEMM (cp.async 2-stage, fp16 x fp16, fp32 accum) -----
// PROVEN R7 shape: 256 threads, 4x2 warps, warp tile 32x32, minBlocks=3.
#define BKC 64
#define RS  72   /* padded row stride in fp16 elems (64 + 8) */

template <int BM, int BN, int WARPS_M, int WARPS_N>
__global__ void __launch_bounds__(WARPS_M * WARPS_N * 32, 3)
gemm_mma_kernel(const __half* __restrict__ A, const __half* __restrict__ B,
                __half* __restrict__ C, int M, int N, int K) {
    constexpr int NT = WARPS_M * WARPS_N * 32;
    constexpr int WM = BM / WARPS_M;           // 32
    constexpr int WN = BN / WARPS_N;           // 32
    constexpr int TM = WM / 16;                // 2
    constexpr int TN2 = WN / 16;               // 2
    constexpr int TN = WN / 8;                 // 4
    constexpr int SA = BM * RS;
    constexpr int SB = BN * RS;
    constexpr int STAGE = SA + SB;

    extern __shared__ __half sm[];
    const uint32_t smb = smem_u32(sm);

    const int tid = threadIdx.x;
    const int wid = tid >> 5, lane = tid & 31;
    const int wm0 = (wid / WARPS_N) * WM;
    const int wn0 = (wid % WARPS_N) * WN;
    const int m0 = blockIdx.y * BM;
    const int n0 = blockIdx.x * BN;
    const int NC = K / BKC;

    float acc[TM][TN][4];
    #pragma unroll
    for (int i = 0; i < TM; i++)
        #pragma unroll
        for (int j = 0; j < TN; j++)
            #pragma unroll
            for (int q = 0; q < 4; q++) acc[i][j][q] = 0.f;

    auto issue = [&](int c) {
        int st = c & 1;
        int kt = c * BKC;
        uint32_t aS = smb + (uint32_t)(st * STAGE) * 2;
        uint32_t bS = aS + SA * 2;
        #pragma unroll
        for (int i = tid; i < BM * 8; i += NT) {
            int row = i >> 3, seg = i & 7;
            int gm = m0 + row;
            int sz = (gm < M) ? 16 : 0;
            int gmc = gm < M ? gm : (M - 1);
            size_t gsrc = (size_t)gmc * K + kt + seg * 8;
            uint32_t so = (uint32_t)(row * RS + seg * 8) * 2;
            cpa16(aS + so, A + gsrc, sz);
        }
        #pragma unroll
        for (int i = tid; i < BN * 8; i += NT) {
            int row = i >> 3, seg = i & 7;
            size_t gsrc = (size_t)(n0 + row) * K + kt + seg * 8;
            uint32_t so = (uint32_t)(row * RS + seg * 8) * 2;
            cpa16(bS + so, B + gsrc, 16);
        }
        CPA_COMMIT();
    };

    const int ldRow = lane & 15;
    const int ldCol = (lane >> 4) * 8;

    issue(0);
    for (int c = 0; c < NC; c++) {
        bool more = (c + 1) < NC;
        if (more) issue(c + 1);
        if (more) asm volatile("cp.async.wait_group 1;" ::: "memory");
        else      asm volatile("cp.async.wait_group 0;" ::: "memory");
        __syncthreads();

        int st = c & 1;
        uint32_t aS = smb + (uint32_t)(st * STAGE) * 2;
        uint32_t bS = aS + SA * 2;

        #pragma unroll
        for (int s = 0; s < 4; s++) {
            const int kb = s * 16;
            uint32_t af[TM][4];
            #pragma unroll
            for (int t = 0; t < TM; t++) {
                uint32_t off = (uint32_t)((wm0 + t * 16 + ldRow) * RS + kb + ldCol) * 2;
                ldsm4(af[t][0], af[t][1], af[t][2], af[t][3], aS + off);
            }
            uint32_t bf[TN2][4];
            #pragma unroll
            for (int t = 0; t < TN2; t++) {
                uint32_t off = (uint32_t)((wn0 + t * 16 + ldRow) * RS + kb + ldCol) * 2;
                ldsm4(bf[t][0], bf[t][1], bf[t][2], bf[t][3], bS + off);
            }
            #pragma unroll
            for (int i = 0; i < TM; i++) {
                #pragma unroll
                for (int j = 0; j < TN; j++) {
                    int t2 = j >> 1, odd = j & 1;
                    mma16816h(acc[i][j], af[i][0], af[i][1], af[i][2], af[i][3],
                              bf[t2][odd], bf[t2][odd + 2]);
                }
            }
        }
        __syncthreads();
    }

    #pragma unroll
    for (int i = 0; i < TM; i++) {
        int r0 = m0 + wm0 + i * 16 + (lane >> 2);
        #pragma unroll
        for (int j = 0; j < TN; j++) {
            int col = n0 + wn0 + j * 8 + (lane & 3) * 2;
            if (r0 < M)
                *(__half2*)&C[(size_t)r0 * N + col] = __floats2half2_rn(acc[i][j][0], acc[i][j][1]);
            if (r0 + 8 < M)
                *(__half2*)&C[(size_t)(r0 + 8) * N + col] = __floats2half2_rn(acc[i][j][2], acc[i][j][3]);
        }
    }
}

// ---------------- layer-1 aggregate + ELU -> fp16 (R7 exact) ----------------
__global__ void __launch_bounds__(128) agg1_kernel() {
    int node = blockIdx.x;
    int tid = threadIdx.x;
    int beg = g_row_start[node], end = g_row_start[node + 1];
    __shared__ int sd[128];

    const __half2* t1h = (const __half2*)g_t1h;   // row = 128 half2
    float ax = 0.f, ay = 0.f;

    for (int base = beg; base < end; base += 128) {
        int n = min(128, end - base);
        if (tid < n) sd[tid] = g_sorted_dst[base + tid];
        __syncthreads();
        int e = 0;
        for (; e + 4 <= n; e += 4) {
            int d0 = sd[e], d1 = sd[e + 1], d2 = sd[e + 2], d3 = sd[e + 3];
            float2 f0 = __half22float2(t1h[(size_t)d0 * 128 + tid]);
            float2 f1 = __half22float2(t1h[(size_t)d1 * 128 + tid]);
            float2 f2 = __half22float2(t1h[(size_t)d2 * 128 + tid]);
            float2 f3 = __half22float2(t1h[(size_t)d3 * 128 + tid]);
            ax += f0.x + f1.x + f2.x + f3.x;
            ay += f0.y + f1.y + f2.y + f3.y;
        }
        for (; e < n; e++) {
            float2 f = __half22float2(t1h[(size_t)sd[e] * 128 + tid]);
            ax += f.x; ay += f.y;
        }
        __syncthreads();
    }
    int deg = end - beg;
    float inv = deg > 0 ? 1.f / (float)deg : 0.f;
    float o0 = eluf(ax * inv), o1 = eluf(ay * inv);
    ((__half2*)g_H16)[(size_t)node * 128 + tid] = __floats2half2_rn(o0, o1);
}

// ---------------- layer-2 aggregate (warp per node, half2 lanes) ------------
__global__ void __launch_bounds__(256) agg2_kernel(float* __restrict__ out) {
    int gw = (blockIdx.x * 256 + threadIdx.x) >> 5;
    int lane = threadIdx.x & 31;
    if (gw >= N_NODES) return;
    int beg = g_row_start[gw], end = g_row_start[gw + 1];

    const __half2* t2h = (const __half2*)g_t2h;   // row = 32 half2
    float ax = 0.f, ay = 0.f;
    for (int eb = beg; eb < end; eb += 32) {
        int n = min(32, end - eb);
        int myd = (lane < n) ? g_sorted_dst[eb + lane] : 0;
        int i = 0;
        for (; i + 2 <= n; i += 2) {
            int d0 = __shfl_sync(0xffffffffu, myd, i);
            int d1 = __shfl_sync(0xffffffffu, myd, i + 1);
            float2 v0 = __half22float2(t2h[(size_t)d0 * 32 + lane]);
            float2 v1 = __half22float2(t2h[(size_t)d1 * 32 + lane]);
            ax += v0.x + v1.x; ay += v0.y + v1.y;
        }
        for (; i < n; i++) {
            int d = __shfl_sync(0xffffffffu, myd, i);
            float2 v = __half22float2(t2h[(size_t)d * 32 + lane]);
            ax += v.x; ay += v.y;
        }
    }
    int deg = end - beg;
    float inv = deg > 0 ? 1.f / (float)deg : 0.f;
    ((float2*)(out + (size_t)gw * D_OUT))[lane] = make_float2(ax * inv, ay * inv);
}

// ---------------- launch (R7 structure: CSR first on s2, dense on main) -----
extern "C" void kernel_launch(void* const* d_in, const int* in_sizes, int n_in,
                              void* d_out, int out_size) {
    const float* X  = (const float*)d_in[0];
    const int*   ei = (const int*)d_in[1];
    const float* W1 = (const float*)d_in[2];
    const float* W2 = (const float*)d_in[3];
    float* out = (float*)d_out;

    void* p;
    cudaGetSymbolAddress(&p, g_t1h); __half* t1 = (__half*)p;
    cudaGetSymbolAddress(&p, g_t2h); __half* t2 = (__half*)p;
    cudaGetSymbolAddress(&p, g_X16); __half* X16 = (__half*)p;
    cudaGetSymbolAddress(&p, g_H16); __half* H16 = (__half*)p;
    cudaGetSymbolAddress(&p, g_B1);  __half* B1 = (__half*)p;
    cudaGetSymbolAddress(&p, g_B2);  __half* B2 = (__half*)p;

    const int SMEM = 2 * (128 + 64) * RS * 2;   // 55296
    static cudaStream_t s2 = nullptr;
    static cudaEvent_t evF = nullptr, evJ = nullptr;
    if (s2 == nullptr) {
        cudaFuncSetAttribute((const void*)gemm_mma_kernel<128, 64, 4, 2>,
                             cudaFuncAttributeMaxDynamicSharedMemorySize, SMEM);
        cudaStreamCreateWithFlags(&s2, cudaStreamNonBlocking);
        cudaEventCreateWithFlags(&evF, cudaEventDisableTiming);
        cudaEventCreateWithFlags(&evJ, cudaEventDisableTiming);
    }

    // ---- fork: CSR chain on s2, dense chain on origin stream ----
    cudaEventRecord(evF, 0);
    cudaStreamWaitEvent(s2, evF, 0);

    zero_counts_kernel<<<(N_NODES + 255) / 256, 256, 0, s2>>>();
    hist_kernel<<<(N_EDGES / 4 + 255) / 256, 256, 0, s2>>>(ei);
    scan1_kernel<<<SCAN_NB, 1024, 0, s2>>>();
    scan2_kernel<<<1, 64, 0, s2>>>();
    scan3_kernel<<<SCAN_NB, 1024, 0, s2>>>();
    scatter_kernel<<<(N_EDGES / 4 + 255) / 256, 256, 0, s2>>>(ei);
    cudaEventRecord(evJ, s2);

    // dense chain (origin stream): fused prep then gemm1
    prep_kernel<<<(NXITEMS + NW1ITEMS + NW2ITEMS + 255) / 256, 256>>>(X, W1, W2);
    {
        dim3 grid(H1 / 64, (N_NODES + 127) / 128);
        gemm_mma_kernel<128, 64, 4, 2><<<grid, 256, SMEM>>>(
            X16, B1, t1, N_NODES, H1, D_IN);
    }

    // ---- join ----
    cudaStreamWaitEvent(0, evJ, 0);

    agg1_kernel<<<N_NODES, 128>>>();
    {
        dim3 grid(1, (N_NODES + 127) / 128);
        gemm_mma_kernel<128, 64, 4, 2><<<grid, 256, SMEM>>>(
            H16, B2, t2, N_NODES, D_OUT, H1);
    }
    agg2_kernel<<<(N_NODES * 32 + 255) / 256, 256>>>(out);
}

// round 13
// speedup vs baseline: 1.1504x; 1.1063x over previous
#include <cuda_runtime.h>
#include <cuda_fp16.h>
#include <math.h>
#include <stdint.h>

#define N_NODES 50000
#define N_EDGES 1600000
#define D_IN    512
#define D_HEAD  64
#define H1      256   /* 4 heads * 64 */
#define D_OUT   64

// ---------------- scratch (device globals; no allocation allowed) ----------
__device__ __half g_t1h[(size_t)N_NODES * H1];          // X @ W1cat (fp16)
__device__ __half g_t2h[(size_t)N_NODES * D_OUT];       // h @ W2 (fp16)
__device__ __half g_X16[(size_t)N_NODES * D_IN];        // fp16 X
__device__ __half g_H16[(size_t)N_NODES * H1];          // elu(agg1) fp16
__device__ __half g_B1[H1 * D_IN];                      // W1 packed [N=256][K=512] fp16
__device__ __half g_B2[D_OUT * H1];                     // W2 packed [N=64][K=256] fp16
__device__ int   g_counts[N_NODES];
__device__ int   g_row_start[N_NODES + 1];
__device__ int   g_cursor[N_NODES];
__device__ int   g_sorted_dst[N_EDGES];
__device__ int   g_bsums[64];
__device__ int   g_boff[64];

// ---------------- helpers ---------------------------------------------------
__device__ __forceinline__ float eluf(float x) { return x > 0.f ? x : expm1f(x); }
__device__ __forceinline__ uint32_t smem_u32(const void* p) {
    uint32_t a;
    asm("{ .reg .u64 t; cvta.to.shared.u64 t, %1; cvt.u32.u64 %0, t; }" : "=r"(a) : "l"(p));
    return a;
}
__device__ __forceinline__ void ldsm4(uint32_t& r0, uint32_t& r1, uint32_t& r2, uint32_t& r3,
                                      uint32_t addr) {
    asm volatile("ldmatrix.sync.aligned.m8n8.x4.shared.b16 {%0,%1,%2,%3}, [%4];"
                 : "=r"(r0), "=r"(r1), "=r"(r2), "=r"(r3) : "r"(addr));
}
__device__ __forceinline__ void mma16816h(float* c, uint32_t a0, uint32_t a1, uint32_t a2,
                                          uint32_t a3, uint32_t b0, uint32_t b1) {
    asm volatile(
        "mma.sync.aligned.m16n8k16.row.col.f32.f16.f16.f32 "
        "{%0,%1,%2,%3}, {%4,%5,%6,%7}, {%8,%9}, {%0,%1,%2,%3};"
        : "+f"(c[0]), "+f"(c[1]), "+f"(c[2]), "+f"(c[3])
        : "r"(a0), "r"(a1), "r"(a2), "r"(a3), "r"(b0), "r"(b1));
}
__device__ __forceinline__ void cpa16(uint32_t saddr, const void* gaddr, int sz) {
    asm volatile("cp.async.cg.shared.global [%0], [%1], 16, %2;"
                 :: "r"(saddr), "l"(gaddr), "r"(sz));
}
#define CPA_COMMIT() asm volatile("cp.async.commit_group;" ::: "memory")

// ---------------- CSR build: histogram -> 3-phase scan -> scatter -----------
__global__ void zero_counts_kernel() {
    int i = blockIdx.x * blockDim.x + threadIdx.x;
    if (i < N_NODES) g_counts[i] = 0;
}
__global__ void hist_kernel(const int* __restrict__ ei) {
    int t = blockIdx.x * blockDim.x + threadIdx.x;
    if (t < N_EDGES / 4) {
        int4 s = ((const int4*)ei)[t];
        atomicAdd(&g_counts[s.x], 1);
        atomicAdd(&g_counts[s.y], 1);
        atomicAdd(&g_counts[s.z], 1);
        atomicAdd(&g_counts[s.w], 1);
    }
}
#define SCAN_NB 49   /* ceil(50000/1024) */
__global__ void __launch_bounds__(1024) scan1_kernel() {
    __shared__ int wsum[32];
    int tid = threadIdx.x, lane = tid & 31, wid = tid >> 5;
    int i = blockIdx.x * 1024 + tid;
    int v = (i < N_NODES) ? g_counts[i] : 0;
    int x = v;
    #pragma unroll
    for (int o = 1; o < 32; o <<= 1) {
        int t = __shfl_up_sync(0xffffffffu, x, o);
        if (lane >= o) x += t;
    }
    if (lane == 31) wsum[wid] = x;
    __syncthreads();
    if (wid == 0) {
        int s = wsum[lane];
        #pragma unroll
        for (int o = 1; o < 32; o <<= 1) {
            int t = __shfl_up_sync(0xffffffffu, s, o);
            if (lane >= o) s += t;
        }
        wsum[lane] = s;
    }
    __syncthreads();
    int boff = (wid > 0) ? wsum[wid - 1] : 0;
    int incl = x + boff;
    if (i < N_NODES) g_row_start[i] = incl - v;
    if (tid == 1023) g_bsums[blockIdx.x] = incl;
}
__global__ void scan2_kernel() {
    __shared__ int sh[64];
    int t = threadIdx.x;
    int v = (t < SCAN_NB) ? g_bsums[t] : 0;
    sh[t] = v;
    __syncthreads();
    #pragma unroll
    for (int o = 1; o < 64; o <<= 1) {
        int val = (t >= o) ? sh[t - o] : 0;
        __syncthreads();
        sh[t] += val;
        __syncthreads();
    }
    if (t < SCAN_NB) g_boff[t] = sh[t] - v;
}
__global__ void __launch_bounds__(1024) scan3_kernel() {
    int i = blockIdx.x * 1024 + threadIdx.x;
    if (i < N_NODES) {
        int rs = g_row_start[i] + g_boff[blockIdx.x];
        g_row_start[i] = rs;
        g_cursor[i] = rs;
    }
    if (i == 0) g_row_start[N_NODES] = N_EDGES;
}
__global__ void scatter_kernel(const int* __restrict__ ei) {
    int t = blockIdx.x * blockDim.x + threadIdx.x;
    if (t < N_EDGES / 4) {
        int4 s = ((const int4*)ei)[t];
        int4 d = ((const int4*)(ei + N_EDGES))[t];
        int p0 = atomicAdd(&g_cursor[s.x], 1);
        int p1 = atomicAdd(&g_cursor[s.y], 1);
        int p2 = atomicAdd(&g_cursor[s.z], 1);
        int p3 = atomicAdd(&g_cursor[s.w], 1);
        g_sorted_dst[p0] = d.x;
        g_sorted_dst[p1] = d.y;
        g_sorted_dst[p2] = d.z;
        g_sorted_dst[p3] = d.w;
    }
}

// ---------------- fused prep: X->fp16 + pack W1 + pack W2 -------------------
#define NXITEMS (N_NODES * D_IN / 4)                 /* 6,400,000 float4 */
#define NW1ITEMS (H1 * D_IN)                         /* 131,072 */
#define NW2ITEMS (D_OUT * H1)                        /* 16,384 */
__global__ void prep_kernel(const float* __restrict__ X,
                            const float* __restrict__ W1,
                            const float* __restrict__ W2) {
    int idx = blockIdx.x * blockDim.x + threadIdx.x;
    if (idx < NXITEMS) {
        float4 v = ((const float4*)X)[idx];
        __half2* ph = (__half2*)g_X16;
        ph[idx * 2 + 0] = __floats2half2_rn(v.x, v.y);
        ph[idx * 2 + 1] = __floats2half2_rn(v.z, v.w);
    } else if (idx < NXITEMS + NW1ITEMS) {
        int i2 = idx - NXITEMS;
        int n = i2 >> 9, k = i2 & 511;
        int head = n >> 6, j = n & 63;
        g_B1[i2] = __float2half_rn(W1[head * (D_IN * D_HEAD) + k * D_HEAD + j]);
    } else if (idx < NXITEMS + NW1ITEMS + NW2ITEMS) {
        int i2 = idx - NXITEMS - NW1ITEMS;
        int n = i2 >> 8, k = i2 & 255;
        g_B2[i2] = __float2half_rn(W2[k * D_OUT + n]);
    }
}

// ---------------- HMMA GEMM (cp.async 2-stage, fp16 x fp16, fp32 accum) -----
// PROVEN R7 shape: 256 threads, 4x2 warps, warp tile 32x32, minBlocks=3.
#define BKC 64
#define RS  72   /* padded row stride in fp16 elems (64 + 8) */

template <int BM, int BN, int WARPS_M, int WARPS_N>
__global__ void __launch_bounds__(WARPS_M * WARPS_N * 32, 3)
gemm_mma_kernel(const __half* __restrict__ A, const __half* __restrict__ B,
                __half* __restrict__ C, int M, int N, int K) {
    constexpr int NT = WARPS_M * WARPS_N * 32;
    constexpr int WM = BM / WARPS_M;           // 32
    constexpr int WN = BN / WARPS_N;           // 32
    constexpr int TM = WM / 16;                // 2
    constexpr int TN2 = WN / 16;               // 2
    constexpr int TN = WN / 8;                 // 4
    constexpr int SA = BM * RS;
    constexpr int SB = BN * RS;
    constexpr int STAGE = SA + SB;

    extern __shared__ __half sm[];
    const uint32_t smb = smem_u32(sm);

    const int tid = threadIdx.x;
    const int wid = tid >> 5, lane = tid & 31;
    const int wm0 = (wid / WARPS_N) * WM;
    const int wn0 = (wid % WARPS_N) * WN;
    const int m0 = blockIdx.y * BM;
    const int n0 = blockIdx.x * BN;
    const int NC = K / BKC;

    float acc[TM][TN][4];
    #pragma unroll
    for (int i = 0; i < TM; i++)
        #pragma unroll
        for (int j = 0; j < TN; j++)
            #pragma unroll
            for (int q = 0; q < 4; q++) acc[i][j][q] = 0.f;

    auto issue = [&](int c) {
        int st = c & 1;
        int kt = c * BKC;
        uint32_t aS = smb + (uint32_t)(st * STAGE) * 2;
        uint32_t bS = aS + SA * 2;
        #pragma unroll
        for (int i = tid; i < BM * 8; i += NT) {
            int row = i >> 3, seg = i & 7;
            int gm = m0 + row;
            int sz = (gm < M) ? 16 : 0;
            int gmc = gm < M ? gm : (M - 1);
            size_t gsrc = (size_t)gmc * K + kt + seg * 8;
            uint32_t so = (uint32_t)(row * RS + seg * 8) * 2;
            cpa16(aS + so, A + gsrc, sz);
        }
        #pragma unroll
        for (int i = tid; i < BN * 8; i += NT) {
            int row = i >> 3, seg = i & 7;
            size_t gsrc = (size_t)(n0 + row) * K + kt + seg * 8;
            uint32_t so = (uint32_t)(row * RS + seg * 8) * 2;
            cpa16(bS + so, B + gsrc, 16);
        }
        CPA_COMMIT();
    };

    const int ldRow = lane & 15;
    const int ldCol = (lane >> 4) * 8;

    issue(0);
    for (int c = 0; c < NC; c++) {
        bool more = (c + 1) < NC;
        if (more) issue(c + 1);
        if (more) asm volatile("cp.async.wait_group 1;" ::: "memory");
        else      asm volatile("cp.async.wait_group 0;" ::: "memory");
        __syncthreads();

        int st = c & 1;
        uint32_t aS = smb + (uint32_t)(st * STAGE) * 2;
        uint32_t bS = aS + SA * 2;

        #pragma unroll
        for (int s = 0; s < 4; s++) {
            const int kb = s * 16;
            uint32_t af[TM][4];
            #pragma unroll
            for (int t = 0; t < TM; t++) {
                uint32_t off = (uint32_t)((wm0 + t * 16 + ldRow) * RS + kb + ldCol) * 2;
                ldsm4(af[t][0], af[t][1], af[t][2], af[t][3], aS + off);
            }
            uint32_t bf[TN2][4];
            #pragma unroll
            for (int t = 0; t < TN2; t++) {
                uint32_t off = (uint32_t)((wn0 + t * 16 + ldRow) * RS + kb + ldCol) * 2;
                ldsm4(bf[t][0], bf[t][1], bf[t][2], bf[t][3], bS + off);
            }
            #pragma unroll
            for (int i = 0; i < TM; i++) {
                #pragma unroll
                for (int j = 0; j < TN; j++) {
                    int t2 = j >> 1, odd = j & 1;
                    mma16816h(acc[i][j], af[i][0], af[i][1], af[i][2], af[i][3],
                              bf[t2][odd], bf[t2][odd + 2]);
                }
            }
        }
        __syncthreads();
    }

    #pragma unroll
    for (int i = 0; i < TM; i++) {
        int r0 = m0 + wm0 + i * 16 + (lane >> 2);
        #pragma unroll
        for (int j = 0; j < TN; j++) {
            int col = n0 + wn0 + j * 8 + (lane & 3) * 2;
            if (r0 < M)
                *(__half2*)&C[(size_t)r0 * N + col] = __floats2half2_rn(acc[i][j][0], acc[i][j][1]);
            if (r0 + 8 < M)
                *(__half2*)&C[(size_t)(r0 + 8) * N + col] = __floats2half2_rn(acc[i][j][2], acc[i][j][3]);
        }
    }
}

// ---------------- layer-1 aggregate + ELU -> fp16 (vectorized) --------------
// 128 threads = 4 warps. Warp w processes neighbors w, w+4, ... Each lane
// loads uint4 (8 fp16 features) -> 4x fewer LDG instructions than the 4B/
// thread version. Cross-warp reduction in smem at the end.
__global__ void __launch_bounds__(128) agg1_kernel() {
    int node = blockIdx.x;
    int tid = threadIdx.x, wid = tid >> 5, lane = tid & 31;
    int beg = g_row_start[node], end = g_row_start[node + 1];
    __shared__ int sd[128];
    __shared__ float red[4][256];

    const uint4* t1v = (const uint4*)g_t1h;   // row = 32 uint4 (256 fp16)
    float acc[8];
    #pragma unroll
    for (int j = 0; j < 8; j++) acc[j] = 0.f;

    for (int base = beg; base < end; base += 128) {
        int n = min(128, end - base);
        if (tid < n) sd[tid] = g_sorted_dst[base + tid];
        __syncthreads();
        int e = wid;
        for (; e + 4 < n; e += 8) {               // 2 neighbors in flight
            int d0 = sd[e], d1 = sd[e + 4];
            uint4 v0 = t1v[(size_t)d0 * 32 + lane];
            uint4 v1 = t1v[(size_t)d1 * 32 + lane];
            const __half2* h0 = (const __half2*)&v0;
            const __half2* h1 = (const __half2*)&v1;
            #pragma unroll
            for (int q = 0; q < 4; q++) {
                float2 a = __half22float2(h0[q]);
                float2 b = __half22float2(h1[q]);
                acc[q * 2 + 0] += a.x + b.x;
                acc[q * 2 + 1] += a.y + b.y;
            }
        }
        if (e < n) {
            int d = sd[e];
            uint4 v = t1v[(size_t)d * 32 + lane];
            const __half2* h = (const __half2*)&v;
            #pragma unroll
            for (int q = 0; q < 4; q++) {
                float2 a = __half22float2(h[q]);
                acc[q * 2 + 0] += a.x;
                acc[q * 2 + 1] += a.y;
            }
        }
        __syncthreads();
    }

    // cross-warp reduce: warp w's lane holds features [lane*8 .. lane*8+8)
    #pragma unroll
    for (int j = 0; j < 8; j++) red[wid][lane * 8 + j] = acc[j];
    __syncthreads();

    int f = tid * 2;        // this thread emits features f, f+1
    float s0 = red[0][f] + red[1][f] + red[2][f] + red[3][f];
    float s1 = red[0][f + 1] + red[1][f + 1] + red[2][f + 1] + red[3][f + 1];
    int deg = end - beg;
    float inv = deg > 0 ? 1.f / (float)deg : 0.f;
    float o0 = eluf(s0 * inv), o1 = eluf(s1 * inv);
    ((__half2*)g_H16)[(size_t)node * 128 + tid] = __floats2half2_rn(o0, o1);
}

// ---------------- layer-2 aggregate (warp per node, half2 lanes) ------------
__global__ void __launch_bounds__(256) agg2_kernel(float* __restrict__ out) {
    int gw = (blockIdx.x * 256 + threadIdx.x) >> 5;
    int lane = threadIdx.x & 31;
    if (gw >= N_NODES) return;
    int beg = g_row_start[gw], end = g_row_start[gw + 1];

    const __half2* t2h = (const __half2*)g_t2h;   // row = 32 half2
    float ax = 0.f, ay = 0.f;
    for (int eb = beg; eb < end; eb += 32) {
        int n = min(32, end - eb);
        int myd = (lane < n) ? g_sorted_dst[eb + lane] : 0;
        int i = 0;
        for (; i + 2 <= n; i += 2) {
            int d0 = __shfl_sync(0xffffffffu, myd, i);
            int d1 = __shfl_sync(0xffffffffu, myd, i + 1);
            float2 v0 = __half22float2(t2h[(size_t)d0 * 32 + lane]);
            float2 v1 = __half22float2(t2h[(size_t)d1 * 32 + lane]);
            ax += v0.x + v1.x; ay += v0.y + v1.y;
        }
        for (; i < n; i++) {
            int d = __shfl_sync(0xffffffffu, myd, i);
            float2 v = __half22float2(t2h[(size_t)d * 32 + lane]);
            ax += v.x; ay += v.y;
        }
    }
    int deg = end - beg;
    float inv = deg > 0 ? 1.f / (float)deg : 0.f;
    ((float2*)(out + (size_t)gw * D_OUT))[lane] = make_float2(ax * inv, ay * inv);
}

// ---------------- launch (R12 structure: CSR first on s2, dense on main) ----
extern "C" void kernel_launch(void* const* d_in, const int* in_sizes, int n_in,
                              void* d_out, int out_size) {
    const float* X  = (const float*)d_in[0];
    const int*   ei = (const int*)d_in[1];
    const float* W1 = (const float*)d_in[2];
    const float* W2 = (const float*)d_in[3];
    float* out = (float*)d_out;

    void* p;
    cudaGetSymbolAddress(&p, g_t1h); __half* t1 = (__half*)p;
    cudaGetSymbolAddress(&p, g_t2h); __half* t2 = (__half*)p;
    cudaGetSymbolAddress(&p, g_X16); __half* X16 = (__half*)p;
    cudaGetSymbolAddress(&p, g_H16); __half* H16 = (__half*)p;
    cudaGetSymbolAddress(&p, g_B1);  __half* B1 = (__half*)p;
    cudaGetSymbolAddress(&p, g_B2);  __half* B2 = (__half*)p;

    const int SMEM = 2 * (128 + 64) * RS * 2;   // 55296
    static cudaStream_t s2 = nullptr;
    static cudaEvent_t evF = nullptr, evJ = nullptr;
    if (s2 == nullptr) {
        cudaFuncSetAttribute((const void*)gemm_mma_kernel<128, 64, 4, 2>,
                             cudaFuncAttributeMaxDynamicSharedMemorySize, SMEM);
        cudaStreamCreateWithFlags(&s2, cudaStreamNonBlocking);
        cudaEventCreateWithFlags(&evF, cudaEventDisableTiming);
        cudaEventCreateWithFlags(&evJ, cudaEventDisableTiming);
    }

    // ---- fork: CSR chain on s2, dense chain on origin stream ----
    cudaEventRecord(evF, 0);
    cudaStreamWaitEvent(s2, evF, 0);

    zero_counts_kernel<<<(N_NODES + 255) / 256, 256, 0, s2>>>();
    hist_kernel<<<(N_EDGES / 4 + 255) / 256, 256, 0, s2>>>(ei);
    scan1_kernel<<<SCAN_NB, 1024, 0, s2>>>();
    scan2_kernel<<<1, 64, 0, s2>>>();
    scan3_kernel<<<SCAN_NB, 1024, 0, s2>>>();
    scatter_kernel<<<(N_EDGES / 4 + 255) / 256, 256, 0, s2>>>(ei);
    cudaEventRecord(evJ, s2);

    // dense chain (origin stream): fused prep then gemm1
    prep_kernel<<<(NXITEMS + NW1ITEMS + NW2ITEMS + 255) / 256, 256>>>(X, W1, W2);
    {
        dim3 grid(H1 / 64, (N_NODES + 127) / 128);
        gemm_mma_kernel<128, 64, 4, 2><<<grid, 256, SMEM>>>(
            X16, B1, t1, N_NODES, H1, D_IN);
    }

    // ---- join ----
    cudaStreamWaitEvent(0, evJ, 0);

    agg1_kernel<<<N_NODES, 128>>>();
    {
        dim3 grid(1, (N_NODES + 127) / 128);
        gemm_mma_kernel<128, 64, 4, 2><<<grid, 256, SMEM>>>(
            H16, B2, t2, N_NODES, D_OUT, H1);
    }
    agg2_kernel<<<(N_NODES * 32 + 255) / 256, 256>>>(out);
}

// round 14
// speedup vs baseline: 1.1919x; 1.0361x over previous
#include <cuda_runtime.h>
#include <cuda_fp16.h>
#include <math.h>
#include <stdint.h>

#define N_NODES 50000
#define N_EDGES 1600000
#define D_IN    512
#define D_HEAD  64
#define H1      256   /* 4 heads * 64 */
#define D_OUT   64

// ---------------- scratch (device globals; no allocation allowed) ----------
__device__ __half g_t1h[(size_t)N_NODES * H1];          // X @ W1cat (fp16)
__device__ __half g_t2h[(size_t)N_NODES * D_OUT];       // h @ W2 (fp16)
__device__ __half g_X16[(size_t)N_NODES * D_IN];        // fp16 X
__device__ __half g_H16[(size_t)N_NODES * H1];          // elu(agg1) fp16
__device__ __half g_B1[H1 * D_IN];                      // W1 packed [N=256][K=512] fp16
__device__ __half g_B2[D_OUT * H1];                     // W2 packed [N=64][K=256] fp16
__device__ int   g_counts[N_NODES];
__device__ int   g_row_start[N_NODES + 1];
__device__ int   g_cursor[N_NODES];
__device__ int   g_sorted_dst[N_EDGES];
__device__ int   g_bsums[64];
__device__ int   g_boff[64];

// ---------------- helpers ---------------------------------------------------
__device__ __forceinline__ float eluf(float x) { return x > 0.f ? x : expm1f(x); }
__device__ __forceinline__ uint32_t smem_u32(const void* p) {
    uint32_t a;
    asm("{ .reg .u64 t; cvta.to.shared.u64 t, %1; cvt.u32.u64 %0, t; }" : "=r"(a) : "l"(p));
    return a;
}
__device__ __forceinline__ void ldsm4(uint32_t& r0, uint32_t& r1, uint32_t& r2, uint32_t& r3,
                                      uint32_t addr) {
    asm volatile("ldmatrix.sync.aligned.m8n8.x4.shared.b16 {%0,%1,%2,%3}, [%4];"
                 : "=r"(r0), "=r"(r1), "=r"(r2), "=r"(r3) : "r"(addr));
}
__device__ __forceinline__ void mma16816h(float* c, uint32_t a0, uint32_t a1, uint32_t a2,
                                          uint32_t a3, uint32_t b0, uint32_t b1) {
    asm volatile(
        "mma.sync.aligned.m16n8k16.row.col.f32.f16.f16.f32 "
        "{%0,%1,%2,%3}, {%4,%5,%6,%7}, {%8,%9}, {%0,%1,%2,%3};"
        : "+f"(c[0]), "+f"(c[1]), "+f"(c[2]), "+f"(c[3])
        : "r"(a0), "r"(a1), "r"(a2), "r"(a3), "r"(b0), "r"(b1));
}
__device__ __forceinline__ void cpa16(uint32_t saddr, const void* gaddr, int sz) {
    asm volatile("cp.async.cg.shared.global [%0], [%1], 16, %2;"
                 :: "r"(saddr), "l"(gaddr), "r"(sz));
}
#define CPA_COMMIT() asm volatile("cp.async.commit_group;" ::: "memory")

// ---------------- CSR build: histogram -> 3-phase scan -> scatter -----------
__global__ void zero_counts_kernel() {
    int i = blockIdx.x * blockDim.x + threadIdx.x;
    if (i < N_NODES) g_counts[i] = 0;
}
__global__ void hist_kernel(const int* __restrict__ ei) {
    int t = blockIdx.x * blockDim.x + threadIdx.x;
    if (t < N_EDGES / 4) {
        int4 s = ((const int4*)ei)[t];
        atomicAdd(&g_counts[s.x], 1);
        atomicAdd(&g_counts[s.y], 1);
        atomicAdd(&g_counts[s.z], 1);
        atomicAdd(&g_counts[s.w], 1);
    }
}
#define SCAN_NB 49   /* ceil(50000/1024) */
__global__ void __launch_bounds__(1024) scan1_kernel() {
    __shared__ int wsum[32];
    int tid = threadIdx.x, lane = tid & 31, wid = tid >> 5;
    int i = blockIdx.x * 1024 + tid;
    int v = (i < N_NODES) ? g_counts[i] : 0;
    int x = v;
    #pragma unroll
    for (int o = 1; o < 32; o <<= 1) {
        int t = __shfl_up_sync(0xffffffffu, x, o);
        if (lane >= o) x += t;
    }
    if (lane == 31) wsum[wid] = x;
    __syncthreads();
    if (wid == 0) {
        int s = wsum[lane];
        #pragma unroll
        for (int o = 1; o < 32; o <<= 1) {
            int t = __shfl_up_sync(0xffffffffu, s, o);
            if (lane >= o) s += t;
        }
        wsum[lane] = s;
    }
    __syncthreads();
    int boff = (wid > 0) ? wsum[wid - 1] : 0;
    int incl = x + boff;
    if (i < N_NODES) g_row_start[i] = incl - v;
    if (tid == 1023) g_bsums[blockIdx.x] = incl;
}
__global__ void scan2_kernel() {
    __shared__ int sh[64];
    int t = threadIdx.x;
    int v = (t < SCAN_NB) ? g_bsums[t] : 0;
    sh[t] = v;
    __syncthreads();
    #pragma unroll
    for (int o = 1; o < 64; o <<= 1) {
        int val = (t >= o) ? sh[t - o] : 0;
        __syncthreads();
        sh[t] += val;
        __syncthreads();
    }
    if (t < SCAN_NB) g_boff[t] = sh[t] - v;
}
__global__ void __launch_bounds__(1024) scan3_kernel() {
    int i = blockIdx.x * 1024 + threadIdx.x;
    if (i < N_NODES) {
        int rs = g_row_start[i] + g_boff[blockIdx.x];
        g_row_start[i] = rs;
        g_cursor[i] = rs;
    }
    if (i == 0) g_row_start[N_NODES] = N_EDGES;
}
__global__ void scatter_kernel(const int* __restrict__ ei) {
    int t = blockIdx.x * blockDim.x + threadIdx.x;
    if (t < N_EDGES / 4) {
        int4 s = ((const int4*)ei)[t];
        int4 d = ((const int4*)(ei + N_EDGES))[t];
        int p0 = atomicAdd(&g_cursor[s.x], 1);
        int p1 = atomicAdd(&g_cursor[s.y], 1);
        int p2 = atomicAdd(&g_cursor[s.z], 1);
        int p3 = atomicAdd(&g_cursor[s.w], 1);
        g_sorted_dst[p0] = d.x;
        g_sorted_dst[p1] = d.y;
        g_sorted_dst[p2] = d.z;
        g_sorted_dst[p3] = d.w;
    }
}

// ---------------- fused prep: X->fp16 + pack W1 + pack W2 -------------------
#define NXITEMS (N_NODES * D_IN / 4)                 /* 6,400,000 float4 */
#define NW1ITEMS (H1 * D_IN)                         /* 131,072 */
#define NW2ITEMS (D_OUT * H1)                        /* 16,384 */
__global__ void prep_kernel(const float* __restrict__ X,
                            const float* __restrict__ W1,
                            const float* __restrict__ W2) {
    int idx = blockIdx.x * blockDim.x + threadIdx.x;
    if (idx < NXITEMS) {
        float4 v = ((const float4*)X)[idx];
        __half2* ph = (__half2*)g_X16;
        ph[idx * 2 + 0] = __floats2half2_rn(v.x, v.y);
        ph[idx * 2 + 1] = __floats2half2_rn(v.z, v.w);
    } else if (idx < NXITEMS + NW1ITEMS) {
        int i2 = idx - NXITEMS;
        int n = i2 >> 9, k = i2 & 511;
        int head = n >> 6, j = n & 63;
        g_B1[i2] = __float2half_rn(W1[head * (D_IN * D_HEAD) + k * D_HEAD + j]);
    } else if (idx < NXITEMS + NW1ITEMS + NW2ITEMS) {
        int i2 = idx - NXITEMS - NW1ITEMS;
        int n = i2 >> 8, k = i2 & 255;
        g_B2[i2] = __float2half_rn(W2[k * D_OUT + n]);
    }
}

// ---------------- HMMA GEMM (cp.async 2-stage, fp16 x fp16, fp32 accum) -----
// PROVEN R7 shape: 256 threads, 4x2 warps, warp tile 32x32, minBlocks=3.
#define BKC 64
#define RS  72   /* padded row stride in fp16 elems (64 + 8) */

template <int BM, int BN, int WARPS_M, int WARPS_N>
__global__ void __launch_bounds__(WARPS_M * WARPS_N * 32, 3)
gemm_mma_kernel(const __half* __restrict__ A, const __half* __restrict__ B,
                __half* __restrict__ C, int M, int N, int K) {
    constexpr int NT = WARPS_M * WARPS_N * 32;
    constexpr int WM = BM / WARPS_M;           // 32
    constexpr int WN = BN / WARPS_N;           // 32
    constexpr int TM = WM / 16;                // 2
    constexpr int TN2 = WN / 16;               // 2
    constexpr int TN = WN / 8;                 // 4
    constexpr int SA = BM * RS;
    constexpr int SB = BN * RS;
    constexpr int STAGE = SA + SB;

    extern __shared__ __half sm[];
    const uint32_t smb = smem_u32(sm);

    const int tid = threadIdx.x;
    const int wid = tid >> 5, lane = tid & 31;
    const int wm0 = (wid / WARPS_N) * WM;
    const int wn0 = (wid % WARPS_N) * WN;
    const int m0 = blockIdx.y * BM;
    const int n0 = blockIdx.x * BN;
    const int NC = K / BKC;

    float acc[TM][TN][4];
    #pragma unroll
    for (int i = 0; i < TM; i++)
        #pragma unroll
        for (int j = 0; j < TN; j++)
            #pragma unroll
            for (int q = 0; q < 4; q++) acc[i][j][q] = 0.f;

    auto issue = [&](int c) {
        int st = c & 1;
        int kt = c * BKC;
        uint32_t aS = smb + (uint32_t)(st * STAGE) * 2;
        uint32_t bS = aS + SA * 2;
        #pragma unroll
        for (int i = tid; i < BM * 8; i += NT) {
            int row = i >> 3, seg = i & 7;
            int gm = m0 + row;
            int sz = (gm < M) ? 16 : 0;
            int gmc = gm < M ? gm : (M - 1);
            size_t gsrc = (size_t)gmc * K + kt + seg * 8;
            uint32_t so = (uint32_t)(row * RS + seg * 8) * 2;
            cpa16(aS + so, A + gsrc, sz);
        }
        #pragma unroll
        for (int i = tid; i < BN * 8; i += NT) {
            int row = i >> 3, seg = i & 7;
            size_t gsrc = (size_t)(n0 + row) * K + kt + seg * 8;
            uint32_t so = (uint32_t)(row * RS + seg * 8) * 2;
            cpa16(bS + so, B + gsrc, 16);
        }
        CPA_COMMIT();
    };

    const int ldRow = lane & 15;
    const int ldCol = (lane >> 4) * 8;

    issue(0);
    for (int c = 0; c < NC; c++) {
        bool more = (c + 1) < NC;
        if (more) issue(c + 1);
        if (more) asm volatile("cp.async.wait_group 1;" ::: "memory");
        else      asm volatile("cp.async.wait_group 0;" ::: "memory");
        __syncthreads();

        int st = c & 1;
        uint32_t aS = smb + (uint32_t)(st * STAGE) * 2;
        uint32_t bS = aS + SA * 2;

        #pragma unroll
        for (int s = 0; s < 4; s++) {
            const int kb = s * 16;
            uint32_t af[TM][4];
            #pragma unroll
            for (int t = 0; t < TM; t++) {
                uint32_t off = (uint32_t)((wm0 + t * 16 + ldRow) * RS + kb + ldCol) * 2;
                ldsm4(af[t][0], af[t][1], af[t][2], af[t][3], aS + off);
            }
            uint32_t bf[TN2][4];
            #pragma unroll
            for (int t = 0; t < TN2; t++) {
                uint32_t off = (uint32_t)((wn0 + t * 16 + ldRow) * RS + kb + ldCol) * 2;
                ldsm4(bf[t][0], bf[t][1], bf[t][2], bf[t][3], bS + off);
            }
            #pragma unroll
            for (int i = 0; i < TM; i++) {
                #pragma unroll
                for (int j = 0; j < TN; j++) {
                    int t2 = j >> 1, odd = j & 1;
                    mma16816h(acc[i][j], af[i][0], af[i][1], af[i][2], af[i][3],
                              bf[t2][odd], bf[t2][odd + 2]);
                }
            }
        }
        __syncthreads();
    }

    #pragma unroll
    for (int i = 0; i < TM; i++) {
        int r0 = m0 + wm0 + i * 16 + (lane >> 2);
        #pragma unroll
        for (int j = 0; j < TN; j++) {
            int col = n0 + wn0 + j * 8 + (lane & 3) * 2;
            if (r0 < M)
                *(__half2*)&C[(size_t)r0 * N + col] = __floats2half2_rn(acc[i][j][0], acc[i][j][1]);
            if (r0 + 8 < M)
                *(__half2*)&C[(size_t)(r0 + 8) * N + col] = __floats2half2_rn(acc[i][j][2], acc[i][j][3]);
        }
    }
}

// ---------------- layer-1 aggregate + ELU -> fp16 (vectorized, R13) ---------
__global__ void __launch_bounds__(128) agg1_kernel() {
    int node = blockIdx.x;
    int tid = threadIdx.x, wid = tid >> 5, lane = tid & 31;
    int beg = g_row_start[node], end = g_row_start[node + 1];
    __shared__ int sd[128];
    __shared__ float red[4][256];

    const uint4* t1v = (const uint4*)g_t1h;   // row = 32 uint4 (256 fp16)
    float acc[8];
    #pragma unroll
    for (int j = 0; j < 8; j++) acc[j] = 0.f;

    for (int base = beg; base < end; base += 128) {
        int n = min(128, end - base);
        if (tid < n) sd[tid] = g_sorted_dst[base + tid];
        __syncthreads();
        int e = wid;
        for (; e + 4 < n; e += 8) {               // 2 neighbors in flight
            int d0 = sd[e], d1 = sd[e + 4];
            uint4 v0 = t1v[(size_t)d0 * 32 + lane];
            uint4 v1 = t1v[(size_t)d1 * 32 + lane];
            const __half2* h0 = (const __half2*)&v0;
            const __half2* h1 = (const __half2*)&v1;
            #pragma unroll
            for (int q = 0; q < 4; q++) {
                float2 a = __half22float2(h0[q]);
                float2 b = __half22float2(h1[q]);
                acc[q * 2 + 0] += a.x + b.x;
                acc[q * 2 + 1] += a.y + b.y;
            }
        }
        if (e < n) {
            int d = sd[e];
            uint4 v = t1v[(size_t)d * 32 + lane];
            const __half2* h = (const __half2*)&v;
            #pragma unroll
            for (int q = 0; q < 4; q++) {
                float2 a = __half22float2(h[q]);
                acc[q * 2 + 0] += a.x;
                acc[q * 2 + 1] += a.y;
            }
        }
        __syncthreads();
    }

    #pragma unroll
    for (int j = 0; j < 8; j++) red[wid][lane * 8 + j] = acc[j];
    __syncthreads();

    int f = tid * 2;
    float s0 = red[0][f] + red[1][f] + red[2][f] + red[3][f];
    float s1 = red[0][f + 1] + red[1][f + 1] + red[2][f + 1] + red[3][f + 1];
    int deg = end - beg;
    float inv = deg > 0 ? 1.f / (float)deg : 0.f;
    float o0 = eluf(s0 * inv), o1 = eluf(s1 * inv);
    ((__half2*)g_H16)[(size_t)node * 128 + tid] = __floats2half2_rn(o0, o1);
}

// ---------------- layer-2 aggregate (warp per node, vectorized) -------------
// 8 lanes x uint4 cover one 128B t2 row -> warp handles 4 neighbors per step.
// Features for lane l are (l&7)*8 .. +8; reduce across neighbor slots with
// shfl_xor 8/16. All shfls full-mask (uniform control flow per warp).
__global__ void __launch_bounds__(256) agg2_kernel(float* __restrict__ out) {
    int gw = (blockIdx.x * 256 + threadIdx.x) >> 5;
    int lane = threadIdx.x & 31;
    if (gw >= N_NODES) return;
    int beg = g_row_start[gw], end = g_row_start[gw + 1];
    int sub = lane >> 3;      // neighbor slot 0..3
    int li  = lane & 7;       // uint4 index within row

    const uint4* t2v = (const uint4*)g_t2h;   // row = 8 uint4 (64 fp16)
    float acc[8];
    #pragma unroll
    for (int j = 0; j < 8; j++) acc[j] = 0.f;

    for (int eb = beg; eb < end; eb += 32) {
        int n = min(32, end - eb);
        int myd = (lane < n) ? g_sorted_dst[eb + lane] : 0;
        int i = 0;
        for (; i + 4 <= n; i += 4) {
            int d = __shfl_sync(0xffffffffu, myd, i + sub);
            uint4 v = t2v[(size_t)d * 8 + li];
            const __half2* h = (const __half2*)&v;
            #pragma unroll
            for (int q = 0; q < 4; q++) {
                float2 a = __half22float2(h[q]);
                acc[q * 2 + 0] += a.x;
                acc[q * 2 + 1] += a.y;
            }
        }
        int rem = n - i;
        if (rem > 0) {
            int pick = i + (sub < rem ? sub : 0);
            int d = __shfl_sync(0xffffffffu, myd, pick);
            if (sub < rem) {
                uint4 v = t2v[(size_t)d * 8 + li];
                const __half2* h = (const __half2*)&v;
                #pragma unroll
                for (int q = 0; q < 4; q++) {
                    float2 a = __half22float2(h[q]);
                    acc[q * 2 + 0] += a.x;
                    acc[q * 2 + 1] += a.y;
                }
            }
        }
    }

    // reduce across the 4 neighbor slots (lanes li, li+8, li+16, li+24)
    #pragma unroll
    for (int j = 0; j < 8; j++) {
        acc[j] += __shfl_xor_sync(0xffffffffu, acc[j], 8);
        acc[j] += __shfl_xor_sync(0xffffffffu, acc[j], 16);
    }

    int deg = end - beg;
    float inv = deg > 0 ? 1.f / (float)deg : 0.f;
    if (sub == 0) {           // lanes 0..7 hold the 64 totals
        float4* dst = (float4*)(out + (size_t)gw * D_OUT + li * 8);
        dst[0] = make_float4(acc[0] * inv, acc[1] * inv, acc[2] * inv, acc[3] * inv);
        dst[1] = make_float4(acc[4] * inv, acc[5] * inv, acc[6] * inv, acc[7] * inv);
    }
}

// ---------------- launch (R13 structure: CSR first on s2, dense on main) ----
extern "C" void kernel_launch(void* const* d_in, const int* in_sizes, int n_in,
                              void* d_out, int out_size) {
    const float* X  = (const float*)d_in[0];
    const int*   ei = (const int*)d_in[1];
    const float* W1 = (const float*)d_in[2];
    const float* W2 = (const float*)d_in[3];
    float* out = (float*)d_out;

    void* p;
    cudaGetSymbolAddress(&p, g_t1h); __half* t1 = (__half*)p;
    cudaGetSymbolAddress(&p, g_t2h); __half* t2 = (__half*)p;
    cudaGetSymbolAddress(&p, g_X16); __half* X16 = (__half*)p;
    cudaGetSymbolAddress(&p, g_H16); __half* H16 = (__half*)p;
    cudaGetSymbolAddress(&p, g_B1);  __half* B1 = (__half*)p;
    cudaGetSymbolAddress(&p, g_B2);  __half* B2 = (__half*)p;

    const int SMEM = 2 * (128 + 64) * RS * 2;   // 55296
    static cudaStream_t s2 = nullptr;
    static cudaEvent_t evF = nullptr, evJ = nullptr;
    if (s2 == nullptr) {
        cudaFuncSetAttribute((const void*)gemm_mma_kernel<128, 64, 4, 2>,
                             cudaFuncAttributeMaxDynamicSharedMemorySize, SMEM);
        cudaStreamCreateWithFlags(&s2, cudaStreamNonBlocking);
        cudaEventCreateWithFlags(&evF, cudaEventDisableTiming);
        cudaEventCreateWithFlags(&evJ, cudaEventDisableTiming);
    }

    // ---- fork: CSR chain on s2, dense chain on origin stream ----
    cudaEventRecord(evF, 0);
    cudaStreamWaitEvent(s2, evF, 0);

    zero_counts_kernel<<<(N_NODES + 255) / 256, 256, 0, s2>>>();
    hist_kernel<<<(N_EDGES / 4 + 255) / 256, 256, 0, s2>>>(ei);
    scan1_kernel<<<SCAN_NB, 1024, 0, s2>>>();
    scan2_kernel<<<1, 64, 0, s2>>>();
    scan3_kernel<<<SCAN_NB, 1024, 0, s2>>>();
    scatter_kernel<<<(N_EDGES / 4 + 255) / 256, 256, 0, s2>>>(ei);
    cudaEventRecord(evJ, s2);

    // dense chain (origin stream): fused prep then gemm1
    prep_kernel<<<(NXITEMS + NW1ITEMS + NW2ITEMS + 255) / 256, 256>>>(X, W1, W2);
    {
        dim3 grid(H1 / 64, (N_NODES + 127) / 128);
        gemm_mma_kernel<128, 64, 4, 2><<<grid, 256, SMEM>>>(
            X16, B1, t1, N_NODES, H1, D_IN);
    }

    // ---- join ----
    cudaStreamWaitEvent(0, evJ, 0);

    agg1_kernel<<<N_NODES, 128>>>();
    {
        dim3 grid(1, (N_NODES + 127) / 128);
        gemm_mma_kernel<128, 64, 4, 2><<<grid, 256, SMEM>>>(
            H16, B2, t2, N_NODES, D_OUT, H1);
    }
    agg2_kernel<<<(N_NODES * 32 + 255) / 256, 256>>>(out);
}